// round 7
// baseline (speedup 1.0000x reference)
#include <cuda_runtime.h>
#include <math.h>

#define Bv 256
#define Tv 256
#define STOCHv 32
#define DETERv 512
#define HIDv 512
#define OBSv 18
#define ACTv 4
#define GATESv 1536
#define OUTCv 1216
#define NB 128          // persistent CTAs (<=148 SMs -> all co-resident)

__device__ float g_xcat[Bv * 1024];        // [b][0:512]=h(t), [512:1024]=deter_in(t)
__device__ float g_gates[2][Bv * GATESv];  // split-K partials
__device__ float g_deter[Bv * DETERv];
__device__ float g_h23[2][Bv * HIDv];      // pre-LN h2 (z=0), h3 (z=1)
__device__ float g_init[DETERv + STOCHv];  // deter0, init_mean
__device__ unsigned g_bar_count;           // zero-init
__device__ unsigned g_bar_gen;             // zero-init

typedef unsigned long long u64;

static __device__ __forceinline__ u64 ffma2(u64 a, u64 b, u64 c) {
    u64 d; asm("fma.rn.f32x2 %0, %1, %2, %3;" : "=l"(d) : "l"(a), "l"(b), "l"(c));
    return d;
}
static __device__ __forceinline__ u64 dup2(float x) {
    u64 r; asm("mov.b64 %0, {%1, %1};" : "=l"(r) : "f"(x)); return r;
}
static __device__ __forceinline__ float sigm(float x)  { return 1.f / (1.f + expf(-x)); }
static __device__ __forceinline__ float siluf(float x) { return x / (1.f + expf(-x)); }
static __device__ __forceinline__ float softp(float x) { return (x > 20.f) ? x : log1pf(expf(x)); }

// sense-reversal grid barrier; all NB CTAs co-resident so spin is safe
static __device__ __forceinline__ void grid_sync() {
    __syncthreads();
    if (threadIdx.x == 0) {
        unsigned gen = *((volatile unsigned*)&g_bar_gen);
        __threadfence();
        if (atomicAdd(&g_bar_count, 1u) == NB - 1) {
            *((volatile unsigned*)&g_bar_count) = 0;
            __threadfence();
            atomicExch(&g_bar_gen, gen + 1);
        } else {
            while (*((volatile unsigned*)&g_bar_gen) == gen) { }
        }
        __threadfence();
    }
    __syncthreads();
}

static __device__ __forceinline__ float block_sum_256(float v, float* red) {
    int lane = threadIdx.x & 31, wid = threadIdx.x >> 5;
#pragma unroll
    for (int o = 16; o; o >>= 1) v += __shfl_xor_sync(0xffffffffu, v, o);
    __syncthreads();
    if (lane == 0) red[wid] = v;
    __syncthreads();
    float s = red[0];
#pragma unroll
    for (int i = 1; i < 8; i++) s += red[i];
    return s;
}

// ---------------- phase bodies (called inside the persistent kernel) --------

static __device__ void initA_body(
    float* sm, float* red,
    const float* __restrict__ initial_deter,
    const float* __restrict__ w_po, const float* __restrict__ g_po, const float* __restrict__ bb_po,
    const float* __restrict__ w_ps, const float* __restrict__ b_ps)
{
    const int tid = threadIdx.x;
    float* d0s = sm;          // 512
    float* h0s = sm + 512;    // 512
    float v0 = tanhf(initial_deter[tid]), v1 = tanhf(initial_deter[tid + 256]);
    d0s[tid] = v0; d0s[tid + 256] = v1;
    g_init[tid] = v0; g_init[tid + 256] = v1;
    __syncthreads();
    float p0 = 0.f, p1 = 0.f;
    for (int k = 0; k < 512; k++) {
        float dv = d0s[k];
        p0 += dv * w_po[(size_t)k * 512 + tid];
        p1 += dv * w_po[(size_t)k * 512 + tid + 256];
    }
    float mean = block_sum_256(p0 + p1, red) * (1.f / 512.f);
    float e0 = p0 - mean, e1 = p1 - mean;
    float var = block_sum_256(e0 * e0 + e1 * e1, red) * (1.f / 512.f);
    float rstd = rsqrtf(var + 1e-3f);
    h0s[tid]       = siluf(e0 * rstd * g_po[tid] + bb_po[tid]);
    h0s[tid + 256] = siluf(e1 * rstd * g_po[tid + 256] + bb_po[tid + 256]);
    __syncthreads();
    if (tid < STOCHv) {
        float s = b_ps[tid];
        for (int k = 0; k < 512; k++) s += h0s[k] * w_ps[(size_t)k * 64 + tid];
        g_init[DETERv + tid] = s;
    }
    __syncthreads();
}

static __device__ void prior_in_body(   // builds xcat h-part for row b from x36
    float* x36, float* red, int b,
    const float* __restrict__ w_pi, const float* __restrict__ g_pi, const float* __restrict__ bb_pi)
{
    const int tid = threadIdx.x;
    float p0 = 0.f, p1 = 0.f;
#pragma unroll
    for (int k = 0; k < 36; k++) {
        float xv = x36[k];
        p0 += xv * w_pi[(size_t)k * HIDv + tid];
        p1 += xv * w_pi[(size_t)k * HIDv + tid + 256];
    }
    float mean = block_sum_256(p0 + p1, red) * (1.f / 512.f);
    float e0 = p0 - mean, e1 = p1 - mean;
    float var = block_sum_256(e0 * e0 + e1 * e1, red) * (1.f / 512.f);
    float rstd = rsqrtf(var + 1e-3f);
    float* xc = g_xcat + (size_t)b * 1024;
    xc[tid]       = siluf(e0 * rstd * g_pi[tid] + bb_pi[tid]);
    xc[tid + 256] = siluf(e1 * rstd * g_pi[tid + 256] + bb_pi[tid + 256]);
}

// gates GEMM [256,1024]@[1024,1536], tile id -> (4 Mtiles, 16 Ntiles, 2 Ksplit)
static __device__ void gates_body(float* sm, int bid, const float* __restrict__ w_gru)
{
    float* As = sm;           // [16][68]
    float* Bs = sm + 1088;    // [16][104]
    const int tid = threadIdx.x;
    const int row0 = (bid & 3) * 64;
    const int col0 = ((bid >> 2) & 15) * 96;
    const int kz   = bid >> 6;
    const int K0   = kz * 512;
    const int tx = tid & 15, ty = tid >> 4;

    u64 acc[4][3];
#pragma unroll
    for (int m = 0; m < 4; m++) { acc[m][0] = acc[m][1] = acc[m][2] = 0ull; }

    const int am = tid >> 2, ak = (tid & 3) * 4;
    const int bk0 = tid / 24, bn0 = (tid % 24) * 4;
    const int bi1 = tid + 256;
    const bool hasB1 = (bi1 < 384);
    const int bk1 = hasB1 ? (bi1 / 24) : 0, bn1 = hasB1 ? ((bi1 % 24) * 4) : 0;

    const float* Ap  = g_xcat + (size_t)(row0 + am) * 1024 + K0 + ak;
    const float* Bp0 = w_gru + (size_t)(K0 + bk0) * GATESv + col0 + bn0;
    const float* Bp1 = w_gru + (size_t)(K0 + bk1) * GATESv + col0 + bn1;

    float4 aL  = *(const float4*)Ap;
    float4 bL0 = *(const float4*)Bp0;
    float4 bL1 = hasB1 ? *(const float4*)Bp1 : make_float4(0.f, 0.f, 0.f, 0.f);

    for (int kt = 0; kt < 32; kt++) {
        As[(ak + 0) * 68 + am] = aL.x; As[(ak + 1) * 68 + am] = aL.y;
        As[(ak + 2) * 68 + am] = aL.z; As[(ak + 3) * 68 + am] = aL.w;
        *(float4*)&Bs[bk0 * 104 + bn0] = bL0;
        if (hasB1) *(float4*)&Bs[bk1 * 104 + bn1] = bL1;
        __syncthreads();
        if (kt + 1 < 32) {
            aL  = *(const float4*)(Ap + (size_t)(kt + 1) * 16);
            bL0 = *(const float4*)(Bp0 + (size_t)(kt + 1) * 16 * GATESv);
            if (hasB1) bL1 = *(const float4*)(Bp1 + (size_t)(kt + 1) * 16 * GATESv);
        }
#pragma unroll
        for (int k = 0; k < 16; k++) {
            float4 a = *(const float4*)&As[k * 68 + ty * 4];
            const u64* bp = (const u64*)&Bs[k * 104 + tx * 6];
            u64 b0 = bp[0], b1 = bp[1], b2 = bp[2];
            u64 a0 = dup2(a.x), a1 = dup2(a.y), a2 = dup2(a.z), a3 = dup2(a.w);
            acc[0][0] = ffma2(a0, b0, acc[0][0]); acc[0][1] = ffma2(a0, b1, acc[0][1]); acc[0][2] = ffma2(a0, b2, acc[0][2]);
            acc[1][0] = ffma2(a1, b0, acc[1][0]); acc[1][1] = ffma2(a1, b1, acc[1][1]); acc[1][2] = ffma2(a1, b2, acc[1][2]);
            acc[2][0] = ffma2(a2, b0, acc[2][0]); acc[2][1] = ffma2(a2, b1, acc[2][1]); acc[2][2] = ffma2(a2, b2, acc[2][2]);
            acc[3][0] = ffma2(a3, b0, acc[3][0]); acc[3][1] = ffma2(a3, b1, acc[3][1]); acc[3][2] = ffma2(a3, b2, acc[3][2]);
        }
        __syncthreads();
    }
#pragma unroll
    for (int m = 0; m < 4; m++) {
        u64* gp = (u64*)&g_gates[kz][(size_t)(row0 + ty * 4 + m) * GATESv + col0 + tx * 6];
        gp[0] = acc[m][0]; gp[1] = acc[m][1]; gp[2] = acc[m][2];
    }
}

static __device__ void gru_row_body(
    float* gs, float* red, int b,
    const float* __restrict__ g_g, const float* __restrict__ bb_g,
    float* __restrict__ out, int t)
{
    const int tid = threadIdx.x;
    const float* p0 = g_gates[0] + (size_t)b * GATESv;
    const float* p1 = g_gates[1] + (size_t)b * GATESv;
    float s = 0.f;
#pragma unroll
    for (int i = 0; i < 6; i++) {
        int c = tid + 256 * i;
        float v = p0[c] + p1[c];
        gs[c] = v; s += v;
    }
    float mean = block_sum_256(s, red) * (1.f / 1536.f);
    float vs = 0.f;
#pragma unroll
    for (int i = 0; i < 6; i++) {
        float e = gs[tid + 256 * i] - mean; vs += e * e;
    }
    float var = block_sum_256(vs, red) * (1.f / 1536.f);
    float rstd = rsqrtf(var + 1e-3f);

    float* ob = out + ((size_t)b * Tv + t) * OUTCv;
    const float* xc = g_xcat + (size_t)b * 1024 + 512;
#pragma unroll
    for (int i = 0; i < 2; i++) {
        int j = tid + 256 * i;
        float gr = (gs[j] - mean) * rstd * g_g[j] + bb_g[j];
        float gc = (gs[j + 512] - mean) * rstd * g_g[j + 512] + bb_g[j + 512];
        float gu = (gs[j + 1024] - mean) * rstd * g_g[j + 1024] + bb_g[j + 1024];
        float r = sigm(gr);
        float u = sigm(gu - 1.0f);
        float cand = siluf(r * gc);
        float d = u * cand + (1.f - u) * xc[j];
        g_deter[(size_t)b * 512 + j] = d;
        ob[j] = d;
        ob[608 + j] = d;
    }
}

// fused prior_out + post GEMMs; tile id -> (8 rowtiles, 8 coltiles, 2 z)
static __device__ void mm_body(
    float* sm, int bid,
    const float* __restrict__ w_po, const float* __restrict__ w_post,
    const float* __restrict__ obs, int t)
{
    float* As = sm;          // [16][36]
    float* Bs = sm + 576;    // [16][72]
    const int tid = threadIdx.x;
    const int row0 = (bid & 7) * 32;
    const int col0 = ((bid >> 3) & 7) * 64;
    const int z    = bid >> 6;
    const int tx = tid & 7, ty = tid >> 3;
    const float* W = z ? w_post : w_po;

    u64 acc[4] = {0ull, 0ull, 0ull, 0ull};

    const int am = tid >> 2, ak = (tid & 3) * 4;   // tid<128 loads A
    const int bk = tid >> 4, bn = (tid & 15) * 4;
    const float* Ap = g_deter + (size_t)(row0 + am) * 512 + ak;
    const float* Bp = W + (size_t)bk * 512 + col0 + bn;

    float4 aL = (tid < 128) ? *(const float4*)Ap : make_float4(0.f, 0.f, 0.f, 0.f);
    float4 bL = *(const float4*)Bp;

    for (int kt = 0; kt < 32; kt++) {
        if (tid < 128) {
            As[(ak + 0) * 36 + am] = aL.x; As[(ak + 1) * 36 + am] = aL.y;
            As[(ak + 2) * 36 + am] = aL.z; As[(ak + 3) * 36 + am] = aL.w;
        }
        *(float4*)&Bs[bk * 72 + bn] = bL;
        __syncthreads();
        if (kt + 1 < 32) {
            if (tid < 128) aL = *(const float4*)(Ap + (size_t)(kt + 1) * 16);
            bL = *(const float4*)(Bp + (size_t)(kt + 1) * 16 * 512);
        }
#pragma unroll
        for (int k = 0; k < 16; k++) {
            u64 av = dup2(As[k * 36 + ty]);
            const u64* bp = (const u64*)&Bs[k * 72 + tx * 8];
            acc[0] = ffma2(av, bp[0], acc[0]);
            acc[1] = ffma2(av, bp[1], acc[1]);
            acc[2] = ffma2(av, bp[2], acc[2]);
            acc[3] = ffma2(av, bp[3], acc[3]);
        }
        __syncthreads();
    }
    if (z == 1) {  // obs tail: K rows 512..529 of w_post
        const int row = row0 + ty;
        const float* op = obs + ((size_t)row * Tv + t) * OBSv;
#pragma unroll
        for (int k = 0; k < OBSv; k++) {
            u64 ov = dup2(op[k]);
            const u64* wp = (const u64*)&w_post[(size_t)(512 + k) * 512 + col0 + tx * 8];
            acc[0] = ffma2(ov, wp[0], acc[0]);
            acc[1] = ffma2(ov, wp[1], acc[1]);
            acc[2] = ffma2(ov, wp[2], acc[2]);
            acc[3] = ffma2(ov, wp[3], acc[3]);
        }
    }
    u64* gp = (u64*)&g_h23[z][(size_t)(row0 + ty) * 512 + col0 + tx * 8];
    gp[0] = acc[0]; gp[1] = acc[1]; gp[2] = acc[2]; gp[3] = acc[3];
}

static __device__ void tail_row_body(
    float* sm, float* red, int b,
    const float* __restrict__ g_po, const float* __restrict__ bb_po,
    const float* __restrict__ g_pq, const float* __restrict__ bb_pq,
    const float* __restrict__ w_ps, const float* __restrict__ b_ps,
    const float* __restrict__ w_qs, const float* __restrict__ b_qs,
    const float* __restrict__ w_pi, const float* __restrict__ g_pi, const float* __restrict__ bb_pi,
    const float* __restrict__ action, const int* __restrict__ is_first,
    float* __restrict__ out, int t)
{
    const int tid = threadIdx.x;
    float* h2  = sm;           // 512
    float* h3  = sm + 512;     // 512
    float* ps  = sm + 1024;    // 64
    float* qs  = sm + 1088;    // 64
    float* x36 = sm + 1152;    // 36

    {
        const float* src = g_h23[0] + (size_t)b * 512;
        float a0 = src[tid], a1 = src[tid + 256];
        float mean = block_sum_256(a0 + a1, red) * (1.f / 512.f);
        float e0 = a0 - mean, e1 = a1 - mean;
        float var = block_sum_256(e0 * e0 + e1 * e1, red) * (1.f / 512.f);
        float rstd = rsqrtf(var + 1e-3f);
        h2[tid]       = siluf(e0 * rstd * g_po[tid] + bb_po[tid]);
        h2[tid + 256] = siluf(e1 * rstd * g_po[tid + 256] + bb_po[tid + 256]);
    }
    {
        const float* src = g_h23[1] + (size_t)b * 512;
        float a0 = src[tid], a1 = src[tid + 256];
        float mean = block_sum_256(a0 + a1, red) * (1.f / 512.f);
        float e0 = a0 - mean, e1 = a1 - mean;
        float var = block_sum_256(e0 * e0 + e1 * e1, red) * (1.f / 512.f);
        float rstd = rsqrtf(var + 1e-3f);
        h3[tid]       = siluf(e0 * rstd * g_pq[tid] + bb_pq[tid]);
        h3[tid + 256] = siluf(e1 * rstd * g_pq[tid + 256] + bb_pq[tid + 256]);
    }
    __syncthreads();

    if (tid < 128) {
        const int j = tid & 63;
        const float* hv = (tid < 64) ? h2 : h3;
        const float* W  = (tid < 64) ? w_ps : w_qs;
        float s = (tid < 64) ? b_ps[j] : b_qs[j];
        for (int k = 0; k < 512; k++) s += hv[k] * W[(size_t)k * 64 + j];
        if (tid < 64) ps[j] = s; else qs[j] = s;
    }
    __syncthreads();

    float* ob = out + ((size_t)b * Tv + t) * OUTCv;
    if (tid < 32) {
        float qm = qs[tid], pm = ps[tid];
        ob[512 + tid] = qm; ob[544 + tid] = qm;
        ob[1120 + tid] = pm; ob[1152 + tid] = pm;
    } else if (tid < 64) {
        int j = tid - 32;
        ob[576 + j]  = softp(qs[tid]) + 0.1f;
        ob[1184 + j] = softp(ps[tid]) + 0.1f;
    }

    if (t + 1 < Tv) {
        const int f = is_first[(size_t)b * Tv + t + 1];
        if (tid < 32) x36[tid] = (f > 0) ? g_init[DETERv + tid] : qs[tid];
        else if (tid < 36) x36[tid] = (f > 0) ? 0.f : action[((size_t)b * Tv + t + 1) * ACTv + (tid - 32)];
        __syncthreads();
        prior_in_body(x36, red, b, w_pi, g_pi, bb_pi);
        float* xc = g_xcat + (size_t)b * 1024;
        const float* dsrc = g_deter + (size_t)b * 512;
        xc[512 + tid]       = (f > 0) ? g_init[tid]       : dsrc[tid];
        xc[512 + tid + 256] = (f > 0) ? g_init[tid + 256] : dsrc[tid + 256];
    }
    __syncthreads();
}

// ---------------- the persistent kernel ----------------
__global__ __launch_bounds__(256, 1) void k_rssm(
    const float* __restrict__ obs, const float* __restrict__ action,
    const int* __restrict__ is_first,
    const float* __restrict__ w_pi, const float* __restrict__ g_pi, const float* __restrict__ bb_pi,
    const float* __restrict__ w_gru, const float* __restrict__ g_g, const float* __restrict__ bb_g,
    const float* __restrict__ w_po, const float* __restrict__ g_po, const float* __restrict__ bb_po,
    const float* __restrict__ w_ps, const float* __restrict__ b_ps,
    const float* __restrict__ w_post, const float* __restrict__ g_pq, const float* __restrict__ bb_pq,
    const float* __restrict__ w_qs, const float* __restrict__ b_qs,
    const float* __restrict__ init_deter,
    float* __restrict__ out)
{
    __shared__ float sm[2760];
    float* red = sm + 2752;
    const int bid = blockIdx.x;
    const int tid = threadIdx.x;

    // init A: deter0 / init_mean (CTA 0 only)
    if (bid == 0)
        initA_body(sm, red, init_deter, w_po, g_po, bb_po, w_ps, b_ps);
    grid_sync();

    // init B: xcat for t=0 (2 rows per CTA)
    {
        float* x36 = sm + 1152;
#pragma unroll
        for (int r = 0; r < 2; r++) {
            const int b = bid * 2 + r;
            const int f = is_first[(size_t)b * Tv];
            if (tid < 32) x36[tid] = g_init[DETERv + tid];
            else if (tid < 36) x36[tid] = (f > 0) ? 0.f : action[(size_t)b * Tv * ACTv + (tid - 32)];
            __syncthreads();
            prior_in_body(x36, red, b, w_pi, g_pi, bb_pi);
            float* xc = g_xcat + (size_t)b * 1024;
            xc[512 + tid]       = g_init[tid];
            xc[512 + tid + 256] = g_init[tid + 256];
            __syncthreads();
        }
    }
    grid_sync();

    for (int t = 0; t < Tv; t++) {
        gates_body(sm, bid, w_gru);
        grid_sync();

#pragma unroll
        for (int r = 0; r < 2; r++) {
            gru_row_body(sm, red, bid * 2 + r, g_g, bb_g, out, t);
            __syncthreads();
        }
        grid_sync();

        mm_body(sm, bid, w_po, w_post, obs, t);
        grid_sync();

#pragma unroll
        for (int r = 0; r < 2; r++) {
            tail_row_body(sm, red, bid * 2 + r,
                          g_po, bb_po, g_pq, bb_pq,
                          w_ps, b_ps, w_qs, b_qs,
                          w_pi, g_pi, bb_pi,
                          action, is_first, out, t);
        }
        grid_sync();
    }
}

extern "C" void kernel_launch(void* const* d_in, const int* in_sizes, int n_in,
                              void* d_out, int out_size)
{
    const float* obs        = (const float*)d_in[0];
    const float* action     = (const float*)d_in[1];
    const int*   is_first   = (const int*)d_in[2];
    const float* w_prior_in = (const float*)d_in[3];
    const float* g_prior_in = (const float*)d_in[4];
    const float* bb_prior_in= (const float*)d_in[5];
    const float* w_gru      = (const float*)d_in[6];
    const float* g_gru_p    = (const float*)d_in[7];
    const float* bb_gru_p   = (const float*)d_in[8];
    const float* w_prior_out= (const float*)d_in[9];
    const float* g_prior_out= (const float*)d_in[10];
    const float* bb_prior_out=(const float*)d_in[11];
    const float* w_prior_st = (const float*)d_in[12];
    const float* b_prior_st = (const float*)d_in[13];
    const float* w_post     = (const float*)d_in[14];
    const float* g_post     = (const float*)d_in[15];
    const float* bb_post    = (const float*)d_in[16];
    const float* w_post_st  = (const float*)d_in[17];
    const float* b_post_st  = (const float*)d_in[18];
    const float* init_deter = (const float*)d_in[19];
    float* out = (float*)d_out;

    k_rssm<<<NB, 256>>>(obs, action, is_first,
                        w_prior_in, g_prior_in, bb_prior_in,
                        w_gru, g_gru_p, bb_gru_p,
                        w_prior_out, g_prior_out, bb_prior_out,
                        w_prior_st, b_prior_st,
                        w_post, g_post, bb_post,
                        w_post_st, b_post_st,
                        init_deter, out);
}

// round 8
// speedup vs baseline: 1.3318x; 1.3318x over previous
#include <cuda_runtime.h>
#include <math.h>

#define Bv 256
#define Tv 256
#define STOCHv 32
#define DETERv 512
#define HIDv 512
#define OBSv 18
#define ACTv 4
#define GATESv 1536
#define OUTCv 1216
#define NB 128          // persistent CTAs, 1/SM, all co-resident

__device__ float g_xcat[Bv * 1024];        // [b][0:512]=h(t), [512:1024]=deter_in(t)
__device__ float g_gates[4][Bv * GATESv];  // gates split-K partials (6MB)
__device__ float g_mm[2][8][Bv * HIDv];    // mm split-K partials (8MB)
__device__ float g_deter[Bv * DETERv];
__device__ float g_init[DETERv + STOCHv];  // deter0, init_mean
__device__ unsigned g_bar_count;
__device__ unsigned g_bar_gen;

typedef unsigned long long u64;

static __device__ __forceinline__ u64 ffma2(u64 a, u64 b, u64 c) {
    u64 d; asm("fma.rn.f32x2 %0, %1, %2, %3;" : "=l"(d) : "l"(a), "l"(b), "l"(c));
    return d;
}
static __device__ __forceinline__ u64 dup2(float x) {
    u64 r; asm("mov.b64 %0, {%1, %1};" : "=l"(r) : "f"(x)); return r;
}
static __device__ __forceinline__ float sigm(float x)  { return 1.f / (1.f + expf(-x)); }
static __device__ __forceinline__ float siluf(float x) { return x / (1.f + expf(-x)); }
static __device__ __forceinline__ float softp(float x) { return (x > 20.f) ? x : log1pf(expf(x)); }

static __device__ __forceinline__ void grid_sync() {
    __syncthreads();
    if (threadIdx.x == 0) {
        unsigned gen = *((volatile unsigned*)&g_bar_gen);
        __threadfence();
        if (atomicAdd(&g_bar_count, 1u) == NB - 1) {
            *((volatile unsigned*)&g_bar_count) = 0;
            __threadfence();
            atomicExch(&g_bar_gen, gen + 1);
        } else {
            while (*((volatile unsigned*)&g_bar_gen) == gen) { }
        }
        __threadfence();
    }
    __syncthreads();
}

static __device__ __forceinline__ float block_sum_256(float v, float* red) {
    int lane = threadIdx.x & 31, wid = threadIdx.x >> 5;
#pragma unroll
    for (int o = 16; o; o >>= 1) v += __shfl_xor_sync(0xffffffffu, v, o);
    __syncthreads();
    if (lane == 0) red[wid] = v;
    __syncthreads();
    float s = red[0];
#pragma unroll
    for (int i = 1; i < 8; i++) s += red[i];
    return s;
}

// ---------------- init A ----------------
static __device__ void initA_body(
    float* sm, float* red,
    const float* __restrict__ initial_deter,
    const float* __restrict__ w_po, const float* __restrict__ g_po, const float* __restrict__ bb_po,
    const float* __restrict__ w_ps, const float* __restrict__ b_ps)
{
    const int tid = threadIdx.x;
    float* d0s = sm;
    float* h0s = sm + 512;
    float v0 = tanhf(initial_deter[tid]), v1 = tanhf(initial_deter[tid + 256]);
    d0s[tid] = v0; d0s[tid + 256] = v1;
    g_init[tid] = v0; g_init[tid + 256] = v1;
    __syncthreads();
    float p0 = 0.f, p1 = 0.f;
    for (int k = 0; k < 512; k++) {
        float dv = d0s[k];
        p0 += dv * w_po[(size_t)k * 512 + tid];
        p1 += dv * w_po[(size_t)k * 512 + tid + 256];
    }
    float mean = block_sum_256(p0 + p1, red) * (1.f / 512.f);
    float e0 = p0 - mean, e1 = p1 - mean;
    float var = block_sum_256(e0 * e0 + e1 * e1, red) * (1.f / 512.f);
    float rstd = rsqrtf(var + 1e-3f);
    h0s[tid]       = siluf(e0 * rstd * g_po[tid] + bb_po[tid]);
    h0s[tid + 256] = siluf(e1 * rstd * g_po[tid + 256] + bb_po[tid + 256]);
    __syncthreads();
    if (tid < STOCHv) {
        float s = b_ps[tid];
        for (int k = 0; k < 512; k++) s += h0s[k] * w_ps[(size_t)k * 64 + tid];
        g_init[DETERv + tid] = s;
    }
    __syncthreads();
}

static __device__ void prior_in_body(
    float* x36, float* red, int b,
    const float* __restrict__ w_pi, const float* __restrict__ g_pi, const float* __restrict__ bb_pi)
{
    const int tid = threadIdx.x;
    float p0 = 0.f, p1 = 0.f;
#pragma unroll
    for (int k = 0; k < 36; k++) {
        float xv = x36[k];
        p0 += xv * w_pi[(size_t)k * HIDv + tid];
        p1 += xv * w_pi[(size_t)k * HIDv + tid + 256];
    }
    float mean = block_sum_256(p0 + p1, red) * (1.f / 512.f);
    float e0 = p0 - mean, e1 = p1 - mean;
    float var = block_sum_256(e0 * e0 + e1 * e1, red) * (1.f / 512.f);
    float rstd = rsqrtf(var + 1e-3f);
    float* xc = g_xcat + (size_t)b * 1024;
    xc[tid]       = siluf(e0 * rstd * g_pi[tid] + bb_pi[tid]);
    xc[tid + 256] = siluf(e1 * rstd * g_pi[tid + 256] + bb_pi[tid + 256]);
}

// gates GEMM [256,1024]@[1024,1536]; 2 Mtiles(128) x 16 Ntiles(96) x ksplit4(K=256)
// thread tile TM=8 x TN=3(u64); A stored DUPLICATED in smem (dup pair read as u64)
static __device__ void gates_body(float* sm, int bid, const float* __restrict__ w_gru)
{
    float* As = sm;          // [16][264]  (dup: 2*128 + 8 pad)
    float* Bs = sm + 4224;   // [16][104]
    const int tid = threadIdx.x;
    const int row0 = (bid & 1) * 128;
    const int col0 = ((bid >> 1) & 15) * 96;
    const int kz   = bid >> 5;
    const int K0   = kz * 256;
    const int tx = tid & 15, ty = tid >> 4;

    u64 acc[8][3];
#pragma unroll
    for (int m = 0; m < 8; m++) { acc[m][0] = acc[m][1] = acc[m][2] = 0ull; }

    const int am = tid >> 1, ak8 = (tid & 1) * 8;
    const int bk0 = tid / 24, bn0 = (tid % 24) * 4;
    const int bi1 = tid + 256;
    const bool hasB1 = (bi1 < 384);
    const int bk1 = hasB1 ? (bi1 / 24) : 0, bn1 = hasB1 ? ((bi1 % 24) * 4) : 0;

    const float* Ap  = g_xcat + (size_t)(row0 + am) * 1024 + K0 + ak8;
    const float* Bp0 = w_gru + (size_t)(K0 + bk0) * GATESv + col0 + bn0;
    const float* Bp1 = w_gru + (size_t)(K0 + bk1) * GATESv + col0 + bn1;

    float4 aL0 = *(const float4*)Ap;
    float4 aL1 = *(const float4*)(Ap + 4);
    float4 bL0 = *(const float4*)Bp0;
    float4 bL1 = hasB1 ? *(const float4*)Bp1 : make_float4(0.f, 0.f, 0.f, 0.f);

    for (int kt = 0; kt < 16; kt++) {
        {
            float v[8] = {aL0.x, aL0.y, aL0.z, aL0.w, aL1.x, aL1.y, aL1.z, aL1.w};
#pragma unroll
            for (int j = 0; j < 8; j++) {
                int idx = (ak8 + j) * 264 + 2 * am;
                As[idx] = v[j]; As[idx + 1] = v[j];
            }
        }
        *(float4*)&Bs[bk0 * 104 + bn0] = bL0;
        if (hasB1) *(float4*)&Bs[bk1 * 104 + bn1] = bL1;
        __syncthreads();
        if (kt + 1 < 16) {
            aL0 = *(const float4*)(Ap + (size_t)(kt + 1) * 16);
            aL1 = *(const float4*)(Ap + (size_t)(kt + 1) * 16 + 4);
            bL0 = *(const float4*)(Bp0 + (size_t)(kt + 1) * 16 * GATESv);
            if (hasB1) bL1 = *(const float4*)(Bp1 + (size_t)(kt + 1) * 16 * GATESv);
        }
#pragma unroll 4
        for (int k = 0; k < 16; k++) {
            const u64* ap = (const u64*)(As + k * 264 + ty * 16);
            const u64* bp = (const u64*)(Bs + k * 104 + tx * 6);
            u64 b0 = bp[0], b1 = bp[1], b2 = bp[2];
#pragma unroll
            for (int m = 0; m < 8; m++) {
                u64 av = ap[m];
                acc[m][0] = ffma2(av, b0, acc[m][0]);
                acc[m][1] = ffma2(av, b1, acc[m][1]);
                acc[m][2] = ffma2(av, b2, acc[m][2]);
            }
        }
        __syncthreads();
    }
#pragma unroll
    for (int m = 0; m < 8; m++) {
        u64* gp = (u64*)&g_gates[kz][(size_t)(row0 + ty * 8 + m) * GATESv + col0 + tx * 6];
        gp[0] = acc[m][0]; gp[1] = acc[m][1]; gp[2] = acc[m][2];
    }
}

static __device__ void gru_row_body(
    float* gs, float* red, int b,
    const float* __restrict__ g_g, const float* __restrict__ bb_g,
    float* __restrict__ out, int t)
{
    const int tid = threadIdx.x;
    const float* p0 = g_gates[0] + (size_t)b * GATESv;
    const float* p1 = g_gates[1] + (size_t)b * GATESv;
    const float* p2 = g_gates[2] + (size_t)b * GATESv;
    const float* p3 = g_gates[3] + (size_t)b * GATESv;
    float s = 0.f;
#pragma unroll
    for (int i = 0; i < 6; i++) {
        int c = tid + 256 * i;
        float v = (p0[c] + p1[c]) + (p2[c] + p3[c]);
        gs[c] = v; s += v;
    }
    float mean = block_sum_256(s, red) * (1.f / 1536.f);
    float vs = 0.f;
#pragma unroll
    for (int i = 0; i < 6; i++) {
        float e = gs[tid + 256 * i] - mean; vs += e * e;
    }
    float var = block_sum_256(vs, red) * (1.f / 1536.f);
    float rstd = rsqrtf(var + 1e-3f);

    float* ob = out + ((size_t)b * Tv + t) * OUTCv;
    const float* xc = g_xcat + (size_t)b * 1024 + 512;
#pragma unroll
    for (int i = 0; i < 2; i++) {
        int j = tid + 256 * i;
        float gr = (gs[j] - mean) * rstd * g_g[j] + bb_g[j];
        float gc = (gs[j + 512] - mean) * rstd * g_g[j + 512] + bb_g[j + 512];
        float gu = (gs[j + 1024] - mean) * rstd * g_g[j + 1024] + bb_g[j + 1024];
        float r = sigm(gr);
        float u = sigm(gu - 1.0f);
        float cand = siluf(r * gc);
        float d = u * cand + (1.f - u) * xc[j];
        g_deter[(size_t)b * 512 + j] = d;
        ob[j] = d;
        ob[608 + j] = d;
    }
}

// mm GEMMs: z=0 prior_out, z=1 post. BM=256 BN=64, ksplit8 (K=64 each, 4 ktiles)
// thread tile TM=8 x TN=4(u64); dup-A in smem. obs tail on z=1,kz=7.
static __device__ void mm_body(
    float* sm, int bid,
    const float* __restrict__ w_po, const float* __restrict__ w_post,
    const float* __restrict__ obs, int t)
{
    float* As = sm;          // [16][520] (dup: 2*256 + 8 pad)
    float* Bs = sm + 8320;   // [16][72]
    const int tid = threadIdx.x;
    const int col0 = (bid & 7) * 64;
    const int z    = (bid >> 3) & 1;
    const int kz   = bid >> 4;
    const int K0   = kz * 64;
    const int tx = tid & 7, ty = tid >> 3;
    const float* W = z ? w_post : w_po;

    u64 acc[8][4];
#pragma unroll
    for (int m = 0; m < 8; m++) { acc[m][0] = acc[m][1] = acc[m][2] = acc[m][3] = 0ull; }

    const int bk = tid >> 4, bn = (tid & 15) * 4;
    const float* Ap = g_deter + (size_t)tid * 512 + K0;
    const float* Bp = W + (size_t)(K0 + bk) * 512 + col0 + bn;

    float4 aL0 = *(const float4*)Ap;
    float4 aL1 = *(const float4*)(Ap + 4);
    float4 aL2 = *(const float4*)(Ap + 8);
    float4 aL3 = *(const float4*)(Ap + 12);
    float4 bL  = *(const float4*)Bp;

    for (int kt = 0; kt < 4; kt++) {
        {
            float v[16] = {aL0.x, aL0.y, aL0.z, aL0.w, aL1.x, aL1.y, aL1.z, aL1.w,
                           aL2.x, aL2.y, aL2.z, aL2.w, aL3.x, aL3.y, aL3.z, aL3.w};
#pragma unroll
            for (int j = 0; j < 16; j++) {
                int idx = j * 520 + 2 * tid;
                As[idx] = v[j]; As[idx + 1] = v[j];
            }
        }
        *(float4*)&Bs[bk * 72 + bn] = bL;
        __syncthreads();
        if (kt + 1 < 4) {
            const float* Apn = Ap + (size_t)(kt + 1) * 16;
            aL0 = *(const float4*)Apn;
            aL1 = *(const float4*)(Apn + 4);
            aL2 = *(const float4*)(Apn + 8);
            aL3 = *(const float4*)(Apn + 12);
            bL  = *(const float4*)(Bp + (size_t)(kt + 1) * 16 * 512);
        }
#pragma unroll 2
        for (int k = 0; k < 16; k++) {
            const u64* ap = (const u64*)(As + k * 520 + ty * 16);
            const u64* bp = (const u64*)(Bs + k * 72 + tx * 8);
            u64 b0 = bp[0], b1 = bp[1], b2 = bp[2], b3 = bp[3];
#pragma unroll
            for (int m = 0; m < 8; m++) {
                u64 av = ap[m];
                acc[m][0] = ffma2(av, b0, acc[m][0]);
                acc[m][1] = ffma2(av, b1, acc[m][1]);
                acc[m][2] = ffma2(av, b2, acc[m][2]);
                acc[m][3] = ffma2(av, b3, acc[m][3]);
            }
        }
        __syncthreads();
    }
    if (z == 1 && kz == 7) {   // obs tail: K rows 512..529 of w_post
#pragma unroll
        for (int m = 0; m < 8; m++) {
            const int row = ty * 8 + m;
            const float* op = obs + ((size_t)row * Tv + t) * OBSv;
            for (int k = 0; k < OBSv; k++) {
                u64 ov = dup2(op[k]);
                const u64* wp = (const u64*)&w_post[(size_t)(512 + k) * 512 + col0 + tx * 8];
                acc[m][0] = ffma2(ov, wp[0], acc[m][0]);
                acc[m][1] = ffma2(ov, wp[1], acc[m][1]);
                acc[m][2] = ffma2(ov, wp[2], acc[m][2]);
                acc[m][3] = ffma2(ov, wp[3], acc[m][3]);
            }
        }
    }
#pragma unroll
    for (int m = 0; m < 8; m++) {
        u64* gp = (u64*)&g_mm[z][kz][(size_t)(ty * 8 + m) * 512 + col0 + tx * 8];
        gp[0] = acc[m][0]; gp[1] = acc[m][1]; gp[2] = acc[m][2]; gp[3] = acc[m][3];
    }
}

static __device__ void tail_row_body(
    float* sm, float* red, int b,
    const float* __restrict__ g_po, const float* __restrict__ bb_po,
    const float* __restrict__ g_pq, const float* __restrict__ bb_pq,
    const float* __restrict__ w_ps, const float* __restrict__ b_ps,
    const float* __restrict__ w_qs, const float* __restrict__ b_qs,
    const float* __restrict__ w_pi, const float* __restrict__ g_pi, const float* __restrict__ bb_pi,
    const float* __restrict__ action, const int* __restrict__ is_first,
    float* __restrict__ out, int t)
{
    const int tid = threadIdx.x;
    float* h2  = sm;
    float* h3  = sm + 512;
    float* ps  = sm + 1024;
    float* qs  = sm + 1088;
    float* x36 = sm + 1152;

#pragma unroll
    for (int z = 0; z < 2; z++) {
        float a0 = 0.f, a1 = 0.f;
#pragma unroll
        for (int kz = 0; kz < 8; kz++) {
            const float* src = g_mm[z][kz] + (size_t)b * 512;
            a0 += src[tid]; a1 += src[tid + 256];
        }
        float mean = block_sum_256(a0 + a1, red) * (1.f / 512.f);
        float e0 = a0 - mean, e1 = a1 - mean;
        float var = block_sum_256(e0 * e0 + e1 * e1, red) * (1.f / 512.f);
        float rstd = rsqrtf(var + 1e-3f);
        const float* gg = z ? g_pq : g_po;
        const float* gb = z ? bb_pq : bb_po;
        float* hv = z ? h3 : h2;
        hv[tid]       = siluf(e0 * rstd * gg[tid] + gb[tid]);
        hv[tid + 256] = siluf(e1 * rstd * gg[tid + 256] + gb[tid + 256]);
        __syncthreads();
    }

    if (tid < 128) {
        const int j = tid & 63;
        const float* hv = (tid < 64) ? h2 : h3;
        const float* W  = (tid < 64) ? w_ps : w_qs;
        float s = (tid < 64) ? b_ps[j] : b_qs[j];
        for (int k = 0; k < 512; k++) s += hv[k] * W[(size_t)k * 64 + j];
        if (tid < 64) ps[j] = s; else qs[j] = s;
    }
    __syncthreads();

    float* ob = out + ((size_t)b * Tv + t) * OUTCv;
    if (tid < 32) {
        float qm = qs[tid], pm = ps[tid];
        ob[512 + tid] = qm; ob[544 + tid] = qm;
        ob[1120 + tid] = pm; ob[1152 + tid] = pm;
    } else if (tid < 64) {
        int j = tid - 32;
        ob[576 + j]  = softp(qs[tid]) + 0.1f;
        ob[1184 + j] = softp(ps[tid]) + 0.1f;
    }

    if (t + 1 < Tv) {
        const int f = is_first[(size_t)b * Tv + t + 1];
        if (tid < 32) x36[tid] = (f > 0) ? g_init[DETERv + tid] : qs[tid];
        else if (tid < 36) x36[tid] = (f > 0) ? 0.f : action[((size_t)b * Tv + t + 1) * ACTv + (tid - 32)];
        __syncthreads();
        prior_in_body(x36, red, b, w_pi, g_pi, bb_pi);
        float* xc = g_xcat + (size_t)b * 1024;
        const float* dsrc = g_deter + (size_t)b * 512;
        xc[512 + tid]       = (f > 0) ? g_init[tid]       : dsrc[tid];
        xc[512 + tid + 256] = (f > 0) ? g_init[tid + 256] : dsrc[tid + 256];
    }
    __syncthreads();
}

// ---------------- persistent kernel ----------------
__global__ __launch_bounds__(256, 1) void k_rssm(
    const float* __restrict__ obs, const float* __restrict__ action,
    const int* __restrict__ is_first,
    const float* __restrict__ w_pi, const float* __restrict__ g_pi, const float* __restrict__ bb_pi,
    const float* __restrict__ w_gru, const float* __restrict__ g_g, const float* __restrict__ bb_g,
    const float* __restrict__ w_po, const float* __restrict__ g_po, const float* __restrict__ bb_po,
    const float* __restrict__ w_ps, const float* __restrict__ b_ps,
    const float* __restrict__ w_post, const float* __restrict__ g_pq, const float* __restrict__ bb_pq,
    const float* __restrict__ w_qs, const float* __restrict__ b_qs,
    const float* __restrict__ init_deter,
    float* __restrict__ out)
{
    __shared__ float sm[9480];
    float* red = sm + 9472;
    const int bid = blockIdx.x;
    const int tid = threadIdx.x;

    if (bid == 0)
        initA_body(sm, red, init_deter, w_po, g_po, bb_po, w_ps, b_ps);
    grid_sync();

    {
        float* x36 = sm + 1152;
#pragma unroll
        for (int r = 0; r < 2; r++) {
            const int b = bid * 2 + r;
            const int f = is_first[(size_t)b * Tv];
            if (tid < 32) x36[tid] = g_init[DETERv + tid];
            else if (tid < 36) x36[tid] = (f > 0) ? 0.f : action[(size_t)b * Tv * ACTv + (tid - 32)];
            __syncthreads();
            prior_in_body(x36, red, b, w_pi, g_pi, bb_pi);
            float* xc = g_xcat + (size_t)b * 1024;
            xc[512 + tid]       = g_init[tid];
            xc[512 + tid + 256] = g_init[tid + 256];
            __syncthreads();
        }
    }
    grid_sync();

    for (int t = 0; t < Tv; t++) {
        gates_body(sm, bid, w_gru);
        grid_sync();

#pragma unroll
        for (int r = 0; r < 2; r++) {
            gru_row_body(sm, red, bid * 2 + r, g_g, bb_g, out, t);
            __syncthreads();
        }
        grid_sync();

        mm_body(sm, bid, w_po, w_post, obs, t);
        grid_sync();

#pragma unroll
        for (int r = 0; r < 2; r++) {
            tail_row_body(sm, red, bid * 2 + r,
                          g_po, bb_po, g_pq, bb_pq,
                          w_ps, b_ps, w_qs, b_qs,
                          w_pi, g_pi, bb_pi,
                          action, is_first, out, t);
        }
        grid_sync();
    }
}

extern "C" void kernel_launch(void* const* d_in, const int* in_sizes, int n_in,
                              void* d_out, int out_size)
{
    const float* obs        = (const float*)d_in[0];
    const float* action     = (const float*)d_in[1];
    const int*   is_first   = (const int*)d_in[2];
    const float* w_prior_in = (const float*)d_in[3];
    const float* g_prior_in = (const float*)d_in[4];
    const float* bb_prior_in= (const float*)d_in[5];
    const float* w_gru      = (const float*)d_in[6];
    const float* g_gru_p    = (const float*)d_in[7];
    const float* bb_gru_p   = (const float*)d_in[8];
    const float* w_prior_out= (const float*)d_in[9];
    const float* g_prior_out= (const float*)d_in[10];
    const float* bb_prior_out=(const float*)d_in[11];
    const float* w_prior_st = (const float*)d_in[12];
    const float* b_prior_st = (const float*)d_in[13];
    const float* w_post     = (const float*)d_in[14];
    const float* g_post     = (const float*)d_in[15];
    const float* bb_post    = (const float*)d_in[16];
    const float* w_post_st  = (const float*)d_in[17];
    const float* b_post_st  = (const float*)d_in[18];
    const float* init_deter = (const float*)d_in[19];
    float* out = (float*)d_out;

    k_rssm<<<NB, 256>>>(obs, action, is_first,
                        w_prior_in, g_prior_in, bb_prior_in,
                        w_gru, g_gru_p, bb_gru_p,
                        w_prior_out, g_prior_out, bb_prior_out,
                        w_prior_st, b_prior_st,
                        w_post, g_post, bb_post,
                        w_post_st, b_post_st,
                        init_deter, out);
}

// round 9
// speedup vs baseline: 1.3973x; 1.0491x over previous
#include <cuda_runtime.h>
#include <math.h>

#define Bv 256
#define Tv 256
#define STOCHv 32
#define DETERv 512
#define HIDv 512
#define OBSv 18
#define ACTv 4
#define GATESv 1536
#define OUTCv 1216
#define NB 256          // persistent CTAs, 128 threads, 2/SM co-resident

__device__ float g_xcat[Bv * 1024];        // [b][0:512]=h(t), [512:1024]=deter_in(t)
__device__ float g_gates[4][Bv * GATESv];  // gates split-K partials
__device__ float g_mm[2][8][Bv * HIDv];    // mm split-K partials
__device__ float g_deter[Bv * DETERv];
__device__ float g_init[DETERv + STOCHv];  // deter0, init_mean
__device__ unsigned g_bar_count;
__device__ unsigned g_bar_gen;

typedef unsigned long long u64;

static __device__ __forceinline__ u64 ffma2(u64 a, u64 b, u64 c) {
    u64 d; asm("fma.rn.f32x2 %0, %1, %2, %3;" : "=l"(d) : "l"(a), "l"(b), "l"(c));
    return d;
}
static __device__ __forceinline__ u64 dup2(float x) {
    u64 r; asm("mov.b64 %0, {%1, %1};" : "=l"(r) : "f"(x)); return r;
}
static __device__ __forceinline__ float sigm(float x)  { return 1.f / (1.f + expf(-x)); }
static __device__ __forceinline__ float siluf(float x) { return x / (1.f + expf(-x)); }
static __device__ __forceinline__ float softp(float x) { return (x > 20.f) ? x : log1pf(expf(x)); }

static __device__ __forceinline__ void grid_sync() {
    __syncthreads();
    if (threadIdx.x == 0) {
        unsigned gen = *((volatile unsigned*)&g_bar_gen);
        __threadfence();
        if (atomicAdd(&g_bar_count, 1u) == NB - 1) {
            *((volatile unsigned*)&g_bar_count) = 0;
            __threadfence();
            atomicExch(&g_bar_gen, gen + 1);
        } else {
            while (*((volatile unsigned*)&g_bar_gen) == gen) { }
        }
        __threadfence();
    }
    __syncthreads();
}

// 128-thread block sum (4 warps)
static __device__ __forceinline__ float block_sum_128(float v, float* red) {
    int lane = threadIdx.x & 31, wid = threadIdx.x >> 5;
#pragma unroll
    for (int o = 16; o; o >>= 1) v += __shfl_xor_sync(0xffffffffu, v, o);
    __syncthreads();
    if (lane == 0) red[wid] = v;
    __syncthreads();
    float s = (red[0] + red[1]) + (red[2] + red[3]);
    return s;
}

// ---------------- init A: deter0 / init_mean (CTA 0) ----------------
static __device__ void initA_body(
    float* sm, float* red,
    const float* __restrict__ initial_deter,
    const float* __restrict__ w_po, const float* __restrict__ g_po, const float* __restrict__ bb_po,
    const float* __restrict__ w_ps, const float* __restrict__ b_ps)
{
    const int tid = threadIdx.x;
    float* d0s = sm;          // 512
    float* h0s = sm + 512;    // 512
#pragma unroll
    for (int i = 0; i < 4; i++) {
        int j = tid + 128 * i;
        float v = tanhf(initial_deter[j]);
        d0s[j] = v; g_init[j] = v;
    }
    __syncthreads();
    float p[4] = {0.f, 0.f, 0.f, 0.f};
    for (int k = 0; k < 512; k++) {
        float dv = d0s[k];
#pragma unroll
        for (int i = 0; i < 4; i++) p[i] += dv * w_po[(size_t)k * 512 + tid + 128 * i];
    }
    float mean = block_sum_128(((p[0] + p[1]) + (p[2] + p[3])), red) * (1.f / 512.f);
    float e[4], vs = 0.f;
#pragma unroll
    for (int i = 0; i < 4; i++) { e[i] = p[i] - mean; vs += e[i] * e[i]; }
    float var = block_sum_128(vs, red) * (1.f / 512.f);
    float rstd = rsqrtf(var + 1e-3f);
#pragma unroll
    for (int i = 0; i < 4; i++) {
        int j = tid + 128 * i;
        h0s[j] = siluf(e[i] * rstd * g_po[j] + bb_po[j]);
    }
    __syncthreads();
    if (tid < STOCHv) {
        float s0 = 0.f, s1 = 0.f, s2 = 0.f, s3 = 0.f;
        for (int k = 0; k < 512; k += 4) {
            s0 += h0s[k]     * w_ps[(size_t)k * 64 + tid];
            s1 += h0s[k + 1] * w_ps[(size_t)(k + 1) * 64 + tid];
            s2 += h0s[k + 2] * w_ps[(size_t)(k + 2) * 64 + tid];
            s3 += h0s[k + 3] * w_ps[(size_t)(k + 3) * 64 + tid];
        }
        g_init[DETERv + tid] = b_ps[tid] + ((s0 + s1) + (s2 + s3));
    }
    __syncthreads();
}

// builds xcat h-part for row b from x36 (smem)
static __device__ void prior_in_body(
    float* x36, float* red, int b,
    const float* __restrict__ w_pi, const float* __restrict__ g_pi, const float* __restrict__ bb_pi)
{
    const int tid = threadIdx.x;
    float p[4] = {0.f, 0.f, 0.f, 0.f};
#pragma unroll
    for (int k = 0; k < 36; k++) {
        float xv = x36[k];
#pragma unroll
        for (int i = 0; i < 4; i++) p[i] += xv * w_pi[(size_t)k * HIDv + tid + 128 * i];
    }
    float mean = block_sum_128(((p[0] + p[1]) + (p[2] + p[3])), red) * (1.f / 512.f);
    float e[4], vs = 0.f;
#pragma unroll
    for (int i = 0; i < 4; i++) { e[i] = p[i] - mean; vs += e[i] * e[i]; }
    float var = block_sum_128(vs, red) * (1.f / 512.f);
    float rstd = rsqrtf(var + 1e-3f);
    float* xc = g_xcat + (size_t)b * 1024;
#pragma unroll
    for (int i = 0; i < 4; i++) {
        int j = tid + 128 * i;
        xc[j] = siluf(e[i] * rstd * g_pi[j] + bb_pi[j]);
    }
}

// gates GEMM [256,1024]@[1024,1536]; 4 Mtiles(64) x 16 Ntiles(96) x ksplit4(K=256)
// 128 threads; thread tile TM=8 x TN=3(u64); dup-A in smem
static __device__ void gates_body(float* sm, int bid, const float* __restrict__ w_gru)
{
    float* As = sm;          // [16][132] (dup 2*64 + 4 pad)
    float* Bs = sm + 2112;   // [16][104]
    const int tid = threadIdx.x;
    const int row0 = (bid & 3) * 64;
    const int col0 = ((bid >> 2) & 15) * 96;
    const int kz   = bid >> 6;
    const int K0   = kz * 256;
    const int tx = tid & 15, ty = tid >> 4;   // ty 0..7

    u64 acc[8][3];
#pragma unroll
    for (int m = 0; m < 8; m++) { acc[m][0] = acc[m][1] = acc[m][2] = 0ull; }

    // A: 64x16 tile = 256 float4, 2/thread (rows ar, ar+32, same kg)
    const int ar = tid >> 2, akg = (tid & 3) * 4;
    // B: 16x96 tile = 384 float4, 3/thread
    const int bk0 = tid / 24,        bn0 = (tid % 24) * 4;
    const int bk1 = (tid + 128) / 24, bn1 = ((tid + 128) % 24) * 4;
    const int bk2 = (tid + 256) / 24, bn2 = ((tid + 256) % 24) * 4;

    const float* Ap0 = g_xcat + (size_t)(row0 + ar) * 1024 + K0 + akg;
    const float* Ap1 = Ap0 + 32 * 1024;
    const float* Bp0 = w_gru + (size_t)(K0 + bk0) * GATESv + col0 + bn0;
    const float* Bp1 = w_gru + (size_t)(K0 + bk1) * GATESv + col0 + bn1;
    const float* Bp2 = w_gru + (size_t)(K0 + bk2) * GATESv + col0 + bn2;

    float4 a0 = *(const float4*)Ap0;
    float4 a1 = *(const float4*)Ap1;
    float4 b0 = *(const float4*)Bp0;
    float4 b1 = *(const float4*)Bp1;
    float4 b2 = *(const float4*)Bp2;

    for (int kt = 0; kt < 16; kt++) {
        {
            float v0[4] = {a0.x, a0.y, a0.z, a0.w};
            float v1[4] = {a1.x, a1.y, a1.z, a1.w};
#pragma unroll
            for (int j = 0; j < 4; j++) {
                *(float2*)&As[(akg + j) * 132 + 2 * ar]        = make_float2(v0[j], v0[j]);
                *(float2*)&As[(akg + j) * 132 + 2 * (ar + 32)] = make_float2(v1[j], v1[j]);
            }
        }
        *(float4*)&Bs[bk0 * 104 + bn0] = b0;
        *(float4*)&Bs[bk1 * 104 + bn1] = b1;
        *(float4*)&Bs[bk2 * 104 + bn2] = b2;
        __syncthreads();
        if (kt + 1 < 16) {
            a0 = *(const float4*)(Ap0 + (size_t)(kt + 1) * 16);
            a1 = *(const float4*)(Ap1 + (size_t)(kt + 1) * 16);
            b0 = *(const float4*)(Bp0 + (size_t)(kt + 1) * 16 * GATESv);
            b1 = *(const float4*)(Bp1 + (size_t)(kt + 1) * 16 * GATESv);
            b2 = *(const float4*)(Bp2 + (size_t)(kt + 1) * 16 * GATESv);
        }
#pragma unroll 4
        for (int k = 0; k < 16; k++) {
            const u64* ap = (const u64*)(As + k * 132 + ty * 16);
            const u64* bp = (const u64*)(Bs + k * 104 + tx * 6);
            u64 bb0 = bp[0], bb1 = bp[1], bb2 = bp[2];
#pragma unroll
            for (int m = 0; m < 8; m++) {
                u64 av = ap[m];
                acc[m][0] = ffma2(av, bb0, acc[m][0]);
                acc[m][1] = ffma2(av, bb1, acc[m][1]);
                acc[m][2] = ffma2(av, bb2, acc[m][2]);
            }
        }
        __syncthreads();
    }
#pragma unroll
    for (int m = 0; m < 8; m++) {
        u64* gp = (u64*)&g_gates[kz][(size_t)(row0 + ty * 8 + m) * GATESv + col0 + tx * 6];
        gp[0] = acc[m][0]; gp[1] = acc[m][1]; gp[2] = acc[m][2];
    }
}

// GRU for row b (1 row per CTA, 128 threads)
static __device__ void gru_row_body(
    float* gs, float* red, int b,
    const float* __restrict__ g_g, const float* __restrict__ bb_g,
    float* __restrict__ out, int t)
{
    const int tid = threadIdx.x;
    const float* p0 = g_gates[0] + (size_t)b * GATESv;
    const float* p1 = g_gates[1] + (size_t)b * GATESv;
    const float* p2 = g_gates[2] + (size_t)b * GATESv;
    const float* p3 = g_gates[3] + (size_t)b * GATESv;
    float s = 0.f;
#pragma unroll
    for (int i = 0; i < 12; i++) {
        int c = tid + 128 * i;
        float v = (p0[c] + p1[c]) + (p2[c] + p3[c]);
        gs[c] = v; s += v;
    }
    float mean = block_sum_128(s, red) * (1.f / 1536.f);
    float vs = 0.f;
#pragma unroll
    for (int i = 0; i < 12; i++) {
        float e = gs[tid + 128 * i] - mean; vs += e * e;
    }
    float var = block_sum_128(vs, red) * (1.f / 1536.f);
    float rstd = rsqrtf(var + 1e-3f);

    float* ob = out + ((size_t)b * Tv + t) * OUTCv;
    const float* xc = g_xcat + (size_t)b * 1024 + 512;
#pragma unroll
    for (int i = 0; i < 4; i++) {
        int j = tid + 128 * i;
        float gr = (gs[j] - mean) * rstd * g_g[j] + bb_g[j];
        float gc = (gs[j + 512] - mean) * rstd * g_g[j + 512] + bb_g[j + 512];
        float gu = (gs[j + 1024] - mean) * rstd * g_g[j + 1024] + bb_g[j + 1024];
        float r = sigm(gr);
        float u = sigm(gu - 1.0f);
        float cand = siluf(r * gc);
        float d = u * cand + (1.f - u) * xc[j];
        g_deter[(size_t)b * 512 + j] = d;
        ob[j] = d;
        ob[608 + j] = d;
    }
}

// mm GEMMs: 2 Mtiles(128) x 8 coltiles(64) x 2 z x ksplit8(K=64)
// 128 threads; thread tile TM=8 x TN=4(u64); dup-A. obs tail on z=1,kz=7.
static __device__ void mm_body(
    float* sm, int bid,
    const float* __restrict__ w_po, const float* __restrict__ w_post,
    const float* __restrict__ obs, int t)
{
    float* As = sm;          // [16][264] (dup 2*128 + 8 pad)
    float* Bs = sm + 4224;   // [16][72]
    const int tid = threadIdx.x;
    const int m2   = bid & 1;
    const int c0   = ((bid >> 1) & 7) * 64;
    const int z    = (bid >> 4) & 1;
    const int kz   = bid >> 5;
    const int K0   = kz * 64;
    const int tx = tid & 7, ty = tid >> 3;   // ty 0..15
    const float* W = z ? w_post : w_po;

    u64 acc[8][4];
#pragma unroll
    for (int m = 0; m < 8; m++) { acc[m][0] = acc[m][1] = acc[m][2] = acc[m][3] = 0ull; }

    // A: 128x16 tile = 512 float4, 4/thread (rows ar + 32i, same kg)
    const int ar = tid >> 2, akg = (tid & 3) * 4;
    // B: 16x64 tile = 256 float4, 2/thread
    const int bk0 = tid >> 4, bn = (tid & 15) * 4;   // bk0 0..7; second slot bk0+8

    const float* ApB = g_deter + (size_t)(m2 * 128 + ar) * 512 + K0 + akg;
    const float* Bp0 = W + (size_t)(K0 + bk0) * 512 + c0 + bn;
    const float* Bp1 = W + (size_t)(K0 + bk0 + 8) * 512 + c0 + bn;

    float4 a0 = *(const float4*)ApB;
    float4 a1 = *(const float4*)(ApB + 32 * 512);
    float4 a2 = *(const float4*)(ApB + 64 * 512);
    float4 a3 = *(const float4*)(ApB + 96 * 512);
    float4 b0 = *(const float4*)Bp0;
    float4 b1 = *(const float4*)Bp1;

    for (int kt = 0; kt < 4; kt++) {
        {
            float v0[4] = {a0.x, a0.y, a0.z, a0.w};
            float v1[4] = {a1.x, a1.y, a1.z, a1.w};
            float v2[4] = {a2.x, a2.y, a2.z, a2.w};
            float v3[4] = {a3.x, a3.y, a3.z, a3.w};
#pragma unroll
            for (int j = 0; j < 4; j++) {
                *(float2*)&As[(akg + j) * 264 + 2 * ar]        = make_float2(v0[j], v0[j]);
                *(float2*)&As[(akg + j) * 264 + 2 * (ar + 32)] = make_float2(v1[j], v1[j]);
                *(float2*)&As[(akg + j) * 264 + 2 * (ar + 64)] = make_float2(v2[j], v2[j]);
                *(float2*)&As[(akg + j) * 264 + 2 * (ar + 96)] = make_float2(v3[j], v3[j]);
            }
        }
        *(float4*)&Bs[bk0 * 72 + bn]       = b0;
        *(float4*)&Bs[(bk0 + 8) * 72 + bn] = b1;
        __syncthreads();
        if (kt + 1 < 4) {
            const float* An = ApB + (size_t)(kt + 1) * 16;
            a0 = *(const float4*)An;
            a1 = *(const float4*)(An + 32 * 512);
            a2 = *(const float4*)(An + 64 * 512);
            a3 = *(const float4*)(An + 96 * 512);
            b0 = *(const float4*)(Bp0 + (size_t)(kt + 1) * 16 * 512);
            b1 = *(const float4*)(Bp1 + (size_t)(kt + 1) * 16 * 512);
        }
#pragma unroll 2
        for (int k = 0; k < 16; k++) {
            const u64* ap = (const u64*)(As + k * 264 + ty * 16);
            const u64* bp = (const u64*)(Bs + k * 72 + tx * 8);
            u64 bb0 = bp[0], bb1 = bp[1], bb2 = bp[2], bb3 = bp[3];
#pragma unroll
            for (int m = 0; m < 8; m++) {
                u64 av = ap[m];
                acc[m][0] = ffma2(av, bb0, acc[m][0]);
                acc[m][1] = ffma2(av, bb1, acc[m][1]);
                acc[m][2] = ffma2(av, bb2, acc[m][2]);
                acc[m][3] = ffma2(av, bb3, acc[m][3]);
            }
        }
        __syncthreads();
    }
    if (z == 1 && kz == 7) {   // obs tail: K rows 512..529 of w_post
#pragma unroll
        for (int m = 0; m < 8; m++) {
            const int row = m2 * 128 + ty * 8 + m;
            const float* op = obs + ((size_t)row * Tv + t) * OBSv;
            for (int k = 0; k < OBSv; k++) {
                u64 ov = dup2(op[k]);
                const u64* wp = (const u64*)&w_post[(size_t)(512 + k) * 512 + c0 + tx * 8];
                acc[m][0] = ffma2(ov, wp[0], acc[m][0]);
                acc[m][1] = ffma2(ov, wp[1], acc[m][1]);
                acc[m][2] = ffma2(ov, wp[2], acc[m][2]);
                acc[m][3] = ffma2(ov, wp[3], acc[m][3]);
            }
        }
    }
#pragma unroll
    for (int m = 0; m < 8; m++) {
        u64* gp = (u64*)&g_mm[z][kz][(size_t)(m2 * 128 + ty * 8 + m) * 512 + c0 + tx * 8];
        gp[0] = acc[m][0]; gp[1] = acc[m][1]; gp[2] = acc[m][2]; gp[3] = acc[m][3];
    }
}

// tail for row b (1 row per CTA)
static __device__ void tail_row_body(
    float* sm, float* red, int b,
    const float* __restrict__ g_po, const float* __restrict__ bb_po,
    const float* __restrict__ g_pq, const float* __restrict__ bb_pq,
    const float* __restrict__ w_ps, const float* __restrict__ b_ps,
    const float* __restrict__ w_qs, const float* __restrict__ b_qs,
    const float* __restrict__ w_pi, const float* __restrict__ g_pi, const float* __restrict__ bb_pi,
    const float* __restrict__ action, const int* __restrict__ is_first,
    float* __restrict__ out, int t)
{
    const int tid = threadIdx.x;
    float* h2  = sm;           // 512
    float* h3  = sm + 512;     // 512
    float* ps  = sm + 1024;    // 64
    float* qs  = sm + 1088;    // 64
    float* x36 = sm + 1152;    // 40

#pragma unroll
    for (int z = 0; z < 2; z++) {
        float a[4] = {0.f, 0.f, 0.f, 0.f};
#pragma unroll
        for (int kzi = 0; kzi < 8; kzi++) {
            const float* src = g_mm[z][kzi] + (size_t)b * 512;
#pragma unroll
            for (int i = 0; i < 4; i++) a[i] += src[tid + 128 * i];
        }
        float mean = block_sum_128(((a[0] + a[1]) + (a[2] + a[3])), red) * (1.f / 512.f);
        float e[4], vs = 0.f;
#pragma unroll
        for (int i = 0; i < 4; i++) { e[i] = a[i] - mean; vs += e[i] * e[i]; }
        float var = block_sum_128(vs, red) * (1.f / 512.f);
        float rstd = rsqrtf(var + 1e-3f);
        const float* gg = z ? g_pq : g_po;
        const float* gb = z ? bb_pq : bb_po;
        float* hv = z ? h3 : h2;
#pragma unroll
        for (int i = 0; i < 4; i++) {
            int j = tid + 128 * i;
            hv[j] = siluf(e[i] * rstd * gg[j] + gb[j]);
        }
        __syncthreads();
    }

    // stats GEMVs: 128 threads -> 128 outputs, 4-way ILP
    {
        const int j = tid & 63;
        const float* hv = (tid < 64) ? h2 : h3;
        const float* W  = (tid < 64) ? w_ps : w_qs;
        float s0 = 0.f, s1 = 0.f, s2 = 0.f, s3 = 0.f;
        for (int k = 0; k < 512; k += 4) {
            s0 += hv[k]     * W[(size_t)k * 64 + j];
            s1 += hv[k + 1] * W[(size_t)(k + 1) * 64 + j];
            s2 += hv[k + 2] * W[(size_t)(k + 2) * 64 + j];
            s3 += hv[k + 3] * W[(size_t)(k + 3) * 64 + j];
        }
        float s = ((tid < 64) ? b_ps[j] : b_qs[j]) + ((s0 + s1) + (s2 + s3));
        if (tid < 64) ps[j] = s; else qs[j] = s;
    }
    __syncthreads();

    float* ob = out + ((size_t)b * Tv + t) * OUTCv;
    if (tid < 32) {
        float qm = qs[tid], pm = ps[tid];
        ob[512 + tid] = qm; ob[544 + tid] = qm;
        ob[1120 + tid] = pm; ob[1152 + tid] = pm;
    } else if (tid < 64) {
        int j = tid - 32;
        ob[576 + j]  = softp(qs[tid]) + 0.1f;
        ob[1184 + j] = softp(ps[tid]) + 0.1f;
    }

    if (t + 1 < Tv) {
        const int f = is_first[(size_t)b * Tv + t + 1];
        if (tid < 32) x36[tid] = (f > 0) ? g_init[DETERv + tid] : qs[tid];
        else if (tid < 36) x36[tid] = (f > 0) ? 0.f : action[((size_t)b * Tv + t + 1) * ACTv + (tid - 32)];
        __syncthreads();
        prior_in_body(x36, red, b, w_pi, g_pi, bb_pi);
        float* xc = g_xcat + (size_t)b * 1024;
        const float* dsrc = g_deter + (size_t)b * 512;
#pragma unroll
        for (int i = 0; i < 4; i++) {
            int j = tid + 128 * i;
            xc[512 + j] = (f > 0) ? g_init[j] : dsrc[j];
        }
    }
    __syncthreads();
}

// ---------------- persistent kernel ----------------
__global__ __launch_bounds__(128, 2) void k_rssm(
    const float* __restrict__ obs, const float* __restrict__ action,
    const int* __restrict__ is_first,
    const float* __restrict__ w_pi, const float* __restrict__ g_pi, const float* __restrict__ bb_pi,
    const float* __restrict__ w_gru, const float* __restrict__ g_g, const float* __restrict__ bb_g,
    const float* __restrict__ w_po, const float* __restrict__ g_po, const float* __restrict__ bb_po,
    const float* __restrict__ w_ps, const float* __restrict__ b_ps,
    const float* __restrict__ w_post, const float* __restrict__ g_pq, const float* __restrict__ bb_pq,
    const float* __restrict__ w_qs, const float* __restrict__ b_qs,
    const float* __restrict__ init_deter,
    float* __restrict__ out)
{
    __shared__ float sm[5384];
    float* red = sm + 5380;
    const int bid = blockIdx.x;
    const int tid = threadIdx.x;

    if (bid == 0)
        initA_body(sm, red, init_deter, w_po, g_po, bb_po, w_ps, b_ps);
    grid_sync();

    // init xcat for t=0 (1 row per CTA)
    {
        float* x36 = sm + 1152;
        const int b = bid;
        const int f = is_first[(size_t)b * Tv];
        if (tid < 32) x36[tid] = g_init[DETERv + tid];
        else if (tid < 36) x36[tid] = (f > 0) ? 0.f : action[(size_t)b * Tv * ACTv + (tid - 32)];
        __syncthreads();
        prior_in_body(x36, red, b, w_pi, g_pi, bb_pi);
        float* xc = g_xcat + (size_t)b * 1024;
#pragma unroll
        for (int i = 0; i < 4; i++) {
            int j = tid + 128 * i;
            xc[512 + j] = g_init[j];
        }
        __syncthreads();
    }
    grid_sync();

    for (int t = 0; t < Tv; t++) {
        gates_body(sm, bid, w_gru);
        grid_sync();

        gru_row_body(sm, red, bid, g_g, bb_g, out, t);
        grid_sync();

        mm_body(sm, bid, w_po, w_post, obs, t);
        grid_sync();

        tail_row_body(sm, red, bid,
                      g_po, bb_po, g_pq, bb_pq,
                      w_ps, b_ps, w_qs, b_qs,
                      w_pi, g_pi, bb_pi,
                      action, is_first, out, t);
        grid_sync();
    }
}

extern "C" void kernel_launch(void* const* d_in, const int* in_sizes, int n_in,
                              void* d_out, int out_size)
{
    const float* obs        = (const float*)d_in[0];
    const float* action     = (const float*)d_in[1];
    const int*   is_first   = (const int*)d_in[2];
    const float* w_prior_in = (const float*)d_in[3];
    const float* g_prior_in = (const float*)d_in[4];
    const float* bb_prior_in= (const float*)d_in[5];
    const float* w_gru      = (const float*)d_in[6];
    const float* g_gru_p    = (const float*)d_in[7];
    const float* bb_gru_p   = (const float*)d_in[8];
    const float* w_prior_out= (const float*)d_in[9];
    const float* g_prior_out= (const float*)d_in[10];
    const float* bb_prior_out=(const float*)d_in[11];
    const float* w_prior_st = (const float*)d_in[12];
    const float* b_prior_st = (const float*)d_in[13];
    const float* w_post     = (const float*)d_in[14];
    const float* g_post     = (const float*)d_in[15];
    const float* bb_post    = (const float*)d_in[16];
    const float* w_post_st  = (const float*)d_in[17];
    const float* b_post_st  = (const float*)d_in[18];
    const float* init_deter = (const float*)d_in[19];
    float* out = (float*)d_out;

    k_rssm<<<NB, 128>>>(obs, action, is_first,
                        w_prior_in, g_prior_in, bb_prior_in,
                        w_gru, g_gru_p, bb_gru_p,
                        w_prior_out, g_prior_out, bb_prior_out,
                        w_prior_st, b_prior_st,
                        w_post, g_post, bb_post,
                        w_post_st, b_post_st,
                        init_deter, out);
}

// round 10
// speedup vs baseline: 1.4657x; 1.0490x over previous
#include <cuda_runtime.h>
#include <math.h>

#define Bv 256
#define Tv 256
#define STOCHv 32
#define DETERv 512
#define HIDv 512
#define OBSv 18
#define ACTv 4
#define GATESv 1536
#define OUTCv 1216
#define NB 256          // persistent CTAs, 256 threads, 2/SM target

__device__ float g_xcat[Bv * 1024];        // [b][0:512]=h(t), [512:1024]=deter_in(t)
__device__ float g_gates[8][Bv * GATESv];  // gates split-K partials
__device__ float g_mm[2][8][Bv * HIDv];    // mm split-K partials
__device__ float g_deter[Bv * DETERv];
__device__ float g_init[DETERv + STOCHv];  // deter0, init_mean
__device__ unsigned g_bar_count;
__device__ unsigned g_bar_gen;

typedef unsigned long long u64;

static __device__ __forceinline__ u64 ffma2(u64 a, u64 b, u64 c) {
    u64 d; asm("fma.rn.f32x2 %0, %1, %2, %3;" : "=l"(d) : "l"(a), "l"(b), "l"(c));
    return d;
}
static __device__ __forceinline__ u64 dup2(float x) {
    u64 r; asm("mov.b64 %0, {%1, %1};" : "=l"(r) : "f"(x)); return r;
}
static __device__ __forceinline__ float sigm(float x)  { return 1.f / (1.f + expf(-x)); }
static __device__ __forceinline__ float siluf(float x) { return x / (1.f + expf(-x)); }
static __device__ __forceinline__ float softp(float x) { return (x > 20.f) ? x : log1pf(expf(x)); }

static __device__ __forceinline__ void grid_sync() {
    __syncthreads();
    if (threadIdx.x == 0) {
        unsigned gen = *((volatile unsigned*)&g_bar_gen);
        __threadfence();
        if (atomicAdd(&g_bar_count, 1u) == NB - 1) {
            *((volatile unsigned*)&g_bar_count) = 0;
            __threadfence();
            atomicExch(&g_bar_gen, gen + 1);
        } else {
            while (*((volatile unsigned*)&g_bar_gen) == gen) { }
        }
        __threadfence();
    }
    __syncthreads();
}

static __device__ __forceinline__ float block_sum_256(float v, float* red) {
    int lane = threadIdx.x & 31, wid = threadIdx.x >> 5;
#pragma unroll
    for (int o = 16; o; o >>= 1) v += __shfl_xor_sync(0xffffffffu, v, o);
    __syncthreads();
    if (lane == 0) red[wid] = v;
    __syncthreads();
    float s = ((red[0] + red[1]) + (red[2] + red[3]))
            + ((red[4] + red[5]) + (red[6] + red[7]));
    return s;
}

// ---------------- init A: deter0 / init_mean (CTA 0, 256 thr) ----------------
static __device__ void initA_body(
    float* sm, float* red,
    const float* __restrict__ initial_deter,
    const float* __restrict__ w_po, const float* __restrict__ g_po, const float* __restrict__ bb_po,
    const float* __restrict__ w_ps, const float* __restrict__ b_ps)
{
    const int tid = threadIdx.x;
    float* d0s = sm;          // 512
    float* h0s = sm + 512;    // 512
#pragma unroll
    for (int i = 0; i < 2; i++) {
        int j = tid + 256 * i;
        float v = tanhf(initial_deter[j]);
        d0s[j] = v; g_init[j] = v;
    }
    __syncthreads();
    float p[2] = {0.f, 0.f};
    for (int k = 0; k < 512; k++) {
        float dv = d0s[k];
#pragma unroll
        for (int i = 0; i < 2; i++) p[i] += dv * w_po[(size_t)k * 512 + tid + 256 * i];
    }
    float mean = block_sum_256(p[0] + p[1], red) * (1.f / 512.f);
    float e[2], vs = 0.f;
#pragma unroll
    for (int i = 0; i < 2; i++) { e[i] = p[i] - mean; vs += e[i] * e[i]; }
    float var = block_sum_256(vs, red) * (1.f / 512.f);
    float rstd = rsqrtf(var + 1e-3f);
#pragma unroll
    for (int i = 0; i < 2; i++) {
        int j = tid + 256 * i;
        h0s[j] = siluf(e[i] * rstd * g_po[j] + bb_po[j]);
    }
    __syncthreads();
    if (tid < STOCHv) {
        float s0 = 0.f, s1 = 0.f, s2 = 0.f, s3 = 0.f;
        for (int k = 0; k < 512; k += 4) {
            s0 += h0s[k]     * w_ps[(size_t)k * 64 + tid];
            s1 += h0s[k + 1] * w_ps[(size_t)(k + 1) * 64 + tid];
            s2 += h0s[k + 2] * w_ps[(size_t)(k + 2) * 64 + tid];
            s3 += h0s[k + 3] * w_ps[(size_t)(k + 3) * 64 + tid];
        }
        g_init[DETERv + tid] = b_ps[tid] + ((s0 + s1) + (s2 + s3));
    }
    __syncthreads();
}

// builds xcat h-part for row b from x36 (smem), 256 thr
static __device__ void prior_in_body(
    float* x36, float* red, int b,
    const float* __restrict__ w_pi, const float* __restrict__ g_pi, const float* __restrict__ bb_pi)
{
    const int tid = threadIdx.x;
    float p[2] = {0.f, 0.f};
#pragma unroll
    for (int k = 0; k < 36; k++) {
        float xv = x36[k];
#pragma unroll
        for (int i = 0; i < 2; i++) p[i] += xv * w_pi[(size_t)k * HIDv + tid + 256 * i];
    }
    float mean = block_sum_256(p[0] + p[1], red) * (1.f / 512.f);
    float e[2], vs = 0.f;
#pragma unroll
    for (int i = 0; i < 2; i++) { e[i] = p[i] - mean; vs += e[i] * e[i]; }
    float var = block_sum_256(vs, red) * (1.f / 512.f);
    float rstd = rsqrtf(var + 1e-3f);
    float* xc = g_xcat + (size_t)b * 1024;
#pragma unroll
    for (int i = 0; i < 2; i++) {
        int j = tid + 256 * i;
        xc[j] = siluf(e[i] * rstd * g_pi[j] + bb_pi[j]);
    }
}

// gates GEMM [256,1024]@[1024,1536]; 2 Mtiles(128) x 16 Ntiles(96) x ksplit8(K=128)
// 256 threads; thread tile TM=8 x TN=3(u64); dup-A in smem
static __device__ void gates_body(float* sm, int bid, const float* __restrict__ w_gru)
{
    float* As = sm;          // [16][260] (dup 2*128 + 4 pad)
    float* Bs = sm + 4160;   // [16][104]
    const int tid = threadIdx.x;
    const int row0 = (bid & 1) * 128;
    const int col0 = ((bid >> 1) & 15) * 96;
    const int kz   = bid >> 5;            // 0..7
    const int K0   = kz * 128;
    const int tx = tid & 15, ty = tid >> 4;   // 16 x 16

    u64 acc[8][3];
#pragma unroll
    for (int m = 0; m < 8; m++) { acc[m][0] = acc[m][1] = acc[m][2] = 0ull; }

    // A: 128 rows x 16 k = 512 float4; 2/thread (same row ar, k halves)
    const int ar = tid >> 1, akg = (tid & 1) * 8;
    // B: 16 k x 96 = 384 float4; slot tid and tid+256 (tid<128)
    const int bk0 = tid / 24,         bn0 = (tid % 24) * 4;
    const bool hasB1 = (tid < 128);
    const int bk1 = (tid + 256) / 24, bn1 = ((tid + 256) % 24) * 4;

    const float* Ap  = g_xcat + (size_t)(row0 + ar) * 1024 + K0 + akg;
    const float* Bp0 = w_gru + (size_t)(K0 + bk0) * GATESv + col0 + bn0;
    const float* Bp1 = w_gru + (size_t)(K0 + bk1) * GATESv + col0 + bn1;

    float4 a0 = *(const float4*)Ap;
    float4 a1 = *(const float4*)(Ap + 4);
    float4 b0 = *(const float4*)Bp0;
    float4 b1 = hasB1 ? *(const float4*)Bp1 : make_float4(0.f, 0.f, 0.f, 0.f);

    for (int kt = 0; kt < 8; kt++) {
        {
            float v[8] = {a0.x, a0.y, a0.z, a0.w, a1.x, a1.y, a1.z, a1.w};
#pragma unroll
            for (int j = 0; j < 8; j++)
                *(float2*)&As[(akg + j) * 260 + 2 * ar] = make_float2(v[j], v[j]);
        }
        *(float4*)&Bs[bk0 * 104 + bn0] = b0;
        if (hasB1) *(float4*)&Bs[bk1 * 104 + bn1] = b1;
        __syncthreads();
        if (kt + 1 < 8) {
            a0 = *(const float4*)(Ap + (size_t)(kt + 1) * 16);
            a1 = *(const float4*)(Ap + (size_t)(kt + 1) * 16 + 4);
            b0 = *(const float4*)(Bp0 + (size_t)(kt + 1) * 16 * GATESv);
            if (hasB1) b1 = *(const float4*)(Bp1 + (size_t)(kt + 1) * 16 * GATESv);
        }
#pragma unroll 4
        for (int k = 0; k < 16; k++) {
            const u64* ap = (const u64*)(As + k * 260) + ty * 8;
            const u64* bp = (const u64*)(Bs + k * 104) + tx * 3;
            u64 bb0 = bp[0], bb1 = bp[1], bb2 = bp[2];
#pragma unroll
            for (int m = 0; m < 8; m++) {
                u64 av = ap[m];
                acc[m][0] = ffma2(av, bb0, acc[m][0]);
                acc[m][1] = ffma2(av, bb1, acc[m][1]);
                acc[m][2] = ffma2(av, bb2, acc[m][2]);
            }
        }
        __syncthreads();
    }
#pragma unroll
    for (int m = 0; m < 8; m++) {
        u64* gp = (u64*)&g_gates[kz][(size_t)(row0 + ty * 8 + m) * GATESv + col0 + tx * 6];
        gp[0] = acc[m][0]; gp[1] = acc[m][1]; gp[2] = acc[m][2];
    }
}

// GRU for row b (1 row/CTA, 256 thr)
static __device__ void gru_row_body(
    float* gs, float* red, int b,
    const float* __restrict__ g_g, const float* __restrict__ bb_g,
    float* __restrict__ out, int t)
{
    const int tid = threadIdx.x;
    float s = 0.f;
#pragma unroll
    for (int i = 0; i < 6; i++) {
        int c = tid + 256 * i;
        float v = 0.f;
#pragma unroll
        for (int kz = 0; kz < 8; kz++) v += g_gates[kz][(size_t)b * GATESv + c];
        gs[c] = v; s += v;
    }
    float mean = block_sum_256(s, red) * (1.f / 1536.f);
    float vs = 0.f;
#pragma unroll
    for (int i = 0; i < 6; i++) {
        float e = gs[tid + 256 * i] - mean; vs += e * e;
    }
    float var = block_sum_256(vs, red) * (1.f / 1536.f);
    float rstd = rsqrtf(var + 1e-3f);

    float* ob = out + ((size_t)b * Tv + t) * OUTCv;
    const float* xc = g_xcat + (size_t)b * 1024 + 512;
#pragma unroll
    for (int i = 0; i < 2; i++) {
        int j = tid + 256 * i;
        float gr = (gs[j] - mean) * rstd * g_g[j] + bb_g[j];
        float gc = (gs[j + 512] - mean) * rstd * g_g[j + 512] + bb_g[j + 512];
        float gu = (gs[j + 1024] - mean) * rstd * g_g[j + 1024] + bb_g[j + 1024];
        float r = sigm(gr);
        float u = sigm(gu - 1.0f);
        float cand = siluf(r * gc);
        float d = u * cand + (1.f - u) * xc[j];
        g_deter[(size_t)b * 512 + j] = d;
        ob[j] = d;
        ob[608 + j] = d;
    }
}

// mm GEMMs: 2 Mtiles(128) x 8 coltiles(64) x 2 z x ksplit8(K=64); 256 thr
// thread tile TM=4 x TN=4(u64); dup-A. obs tail on z=1,kz=7.
static __device__ void mm_body(
    float* sm, int bid,
    const float* __restrict__ w_po, const float* __restrict__ w_post,
    const float* __restrict__ obs, int t)
{
    float* As = sm;          // [16][260]
    float* Bs = sm + 4160;   // [16][72]
    const int tid = threadIdx.x;
    const int m2   = bid & 1;
    const int c0   = ((bid >> 1) & 7) * 64;
    const int z    = (bid >> 4) & 1;
    const int kz   = bid >> 5;           // 0..7
    const int K0   = kz * 64;
    const int tx = tid & 7, ty = tid >> 3;   // 8 x 32
    const float* W = z ? w_post : w_po;

    u64 acc[4][4];
#pragma unroll
    for (int m = 0; m < 4; m++) { acc[m][0] = acc[m][1] = acc[m][2] = acc[m][3] = 0ull; }

    const int ar = tid >> 1, akg = (tid & 1) * 8;
    const int bk = tid >> 4, bn = (tid & 15) * 4;     // 16k x 64 = 256 f4, 1/thread

    const float* Ap = g_deter + (size_t)(m2 * 128 + ar) * 512 + K0 + akg;
    const float* Bp = W + (size_t)(K0 + bk) * 512 + c0 + bn;

    float4 a0 = *(const float4*)Ap;
    float4 a1 = *(const float4*)(Ap + 4);
    float4 b0 = *(const float4*)Bp;

    for (int kt = 0; kt < 4; kt++) {
        {
            float v[8] = {a0.x, a0.y, a0.z, a0.w, a1.x, a1.y, a1.z, a1.w};
#pragma unroll
            for (int j = 0; j < 8; j++)
                *(float2*)&As[(akg + j) * 260 + 2 * ar] = make_float2(v[j], v[j]);
        }
        *(float4*)&Bs[bk * 72 + bn] = b0;
        __syncthreads();
        if (kt + 1 < 4) {
            a0 = *(const float4*)(Ap + (size_t)(kt + 1) * 16);
            a1 = *(const float4*)(Ap + (size_t)(kt + 1) * 16 + 4);
            b0 = *(const float4*)(Bp + (size_t)(kt + 1) * 16 * 512);
        }
#pragma unroll 4
        for (int k = 0; k < 16; k++) {
            const u64* ap = (const u64*)(As + k * 260) + ty * 4;
            const u64* bp = (const u64*)(Bs + k * 72) + tx * 4;
            u64 bb0 = bp[0], bb1 = bp[1], bb2 = bp[2], bb3 = bp[3];
#pragma unroll
            for (int m = 0; m < 4; m++) {
                u64 av = ap[m];
                acc[m][0] = ffma2(av, bb0, acc[m][0]);
                acc[m][1] = ffma2(av, bb1, acc[m][1]);
                acc[m][2] = ffma2(av, bb2, acc[m][2]);
                acc[m][3] = ffma2(av, bb3, acc[m][3]);
            }
        }
        __syncthreads();
    }
    if (z == 1 && kz == 7) {   // obs tail: K rows 512..529
#pragma unroll
        for (int m = 0; m < 4; m++) {
            const int row = m2 * 128 + ty * 4 + m;
            const float* op = obs + ((size_t)row * Tv + t) * OBSv;
            for (int k = 0; k < OBSv; k++) {
                u64 ov = dup2(op[k]);
                const u64* wp = (const u64*)&w_post[(size_t)(512 + k) * 512 + c0 + tx * 8];
                acc[m][0] = ffma2(ov, wp[0], acc[m][0]);
                acc[m][1] = ffma2(ov, wp[1], acc[m][1]);
                acc[m][2] = ffma2(ov, wp[2], acc[m][2]);
                acc[m][3] = ffma2(ov, wp[3], acc[m][3]);
            }
        }
    }
#pragma unroll
    for (int m = 0; m < 4; m++) {
        u64* gp = (u64*)&g_mm[z][kz][(size_t)(m2 * 128 + ty * 4 + m) * 512 + c0 + tx * 8];
        gp[0] = acc[m][0]; gp[1] = acc[m][1]; gp[2] = acc[m][2]; gp[3] = acc[m][3];
    }
}

// tail for row b (1 row/CTA, 256 thr)
static __device__ void tail_row_body(
    float* sm, float* red, int b,
    const float* __restrict__ g_po, const float* __restrict__ bb_po,
    const float* __restrict__ g_pq, const float* __restrict__ bb_pq,
    const float* __restrict__ w_ps, const float* __restrict__ b_ps,
    const float* __restrict__ w_qs, const float* __restrict__ b_qs,
    const float* __restrict__ w_pi, const float* __restrict__ g_pi, const float* __restrict__ bb_pi,
    const float* __restrict__ action, const int* __restrict__ is_first,
    float* __restrict__ out, int t)
{
    const int tid = threadIdx.x;
    float* h2  = sm;           // 512
    float* h3  = sm + 512;     // 512
    float* ps  = sm + 1024;    // 64
    float* qs  = sm + 1088;    // 64
    float* pp  = sm + 1152;    // 256 (stats split-k partials)
    float* x36 = sm + 1408;    // 40

#pragma unroll
    for (int z = 0; z < 2; z++) {
        float a[2] = {0.f, 0.f};
#pragma unroll
        for (int kzi = 0; kzi < 8; kzi++) {
            const float* src = g_mm[z][kzi] + (size_t)b * 512;
            a[0] += src[tid]; a[1] += src[tid + 256];
        }
        float mean = block_sum_256(a[0] + a[1], red) * (1.f / 512.f);
        float e[2], vs = 0.f;
#pragma unroll
        for (int i = 0; i < 2; i++) { e[i] = a[i] - mean; vs += e[i] * e[i]; }
        float var = block_sum_256(vs, red) * (1.f / 512.f);
        float rstd = rsqrtf(var + 1e-3f);
        const float* gg = z ? g_pq : g_po;
        const float* gb = z ? bb_pq : bb_po;
        float* hv = z ? h3 : h2;
#pragma unroll
        for (int i = 0; i < 2; i++) {
            int j = tid + 256 * i;
            hv[j] = siluf(e[i] * rstd * gg[j] + gb[j]);
        }
        __syncthreads();
    }

    // stats GEMVs: 128 outputs, split-K across thread halves
    {
        const int half = tid >> 7;        // 0: k<256, 1: k>=256
        const int tl   = tid & 127;
        const int j    = tl & 63;
        const float* hv = (tl < 64) ? h2 : h3;
        const float* W  = (tl < 64) ? w_ps : w_qs;
        const int kbase = half * 256;
        float s0 = 0.f, s1 = 0.f, s2 = 0.f, s3 = 0.f;
        for (int k = 0; k < 256; k += 4) {
            int kk = kbase + k;
            s0 += hv[kk]     * W[(size_t)kk * 64 + j];
            s1 += hv[kk + 1] * W[(size_t)(kk + 1) * 64 + j];
            s2 += hv[kk + 2] * W[(size_t)(kk + 2) * 64 + j];
            s3 += hv[kk + 3] * W[(size_t)(kk + 3) * 64 + j];
        }
        pp[tid] = (s0 + s1) + (s2 + s3);
    }
    __syncthreads();
    if (tid < 128) {
        const int j = tid & 63;
        float s = (pp[tid] + pp[tid + 128]) + ((tid < 64) ? b_ps[j] : b_qs[j]);
        if (tid < 64) ps[j] = s; else qs[j] = s;
    }
    __syncthreads();

    float* ob = out + ((size_t)b * Tv + t) * OUTCv;
    if (tid < 32) {
        float qm = qs[tid], pm = ps[tid];
        ob[512 + tid] = qm; ob[544 + tid] = qm;
        ob[1120 + tid] = pm; ob[1152 + tid] = pm;
    } else if (tid < 64) {
        int j = tid - 32;
        ob[576 + j]  = softp(qs[tid]) + 0.1f;
        ob[1184 + j] = softp(ps[tid]) + 0.1f;
    }

    if (t + 1 < Tv) {
        const int f = is_first[(size_t)b * Tv + t + 1];
        if (tid < 32) x36[tid] = (f > 0) ? g_init[DETERv + tid] : qs[tid];
        else if (tid < 36) x36[tid] = (f > 0) ? 0.f : action[((size_t)b * Tv + t + 1) * ACTv + (tid - 32)];
        __syncthreads();
        prior_in_body(x36, red, b, w_pi, g_pi, bb_pi);
        float* xc = g_xcat + (size_t)b * 1024;
        const float* dsrc = g_deter + (size_t)b * 512;
#pragma unroll
        for (int i = 0; i < 2; i++) {
            int j = tid + 256 * i;
            xc[512 + j] = (f > 0) ? g_init[j] : dsrc[j];
        }
    }
    __syncthreads();
}

// ---------------- persistent kernel ----------------
__global__ __launch_bounds__(256, 2) void k_rssm(
    const float* __restrict__ obs, const float* __restrict__ action,
    const int* __restrict__ is_first,
    const float* __restrict__ w_pi, const float* __restrict__ g_pi, const float* __restrict__ bb_pi,
    const float* __restrict__ w_gru, const float* __restrict__ g_g, const float* __restrict__ bb_g,
    const float* __restrict__ w_po, const float* __restrict__ g_po, const float* __restrict__ bb_po,
    const float* __restrict__ w_ps, const float* __restrict__ b_ps,
    const float* __restrict__ w_post, const float* __restrict__ g_pq, const float* __restrict__ bb_pq,
    const float* __restrict__ w_qs, const float* __restrict__ b_qs,
    const float* __restrict__ init_deter,
    float* __restrict__ out)
{
    __shared__ float sm[5832];
    float* red = sm + 5824;
    const int bid = blockIdx.x;
    const int tid = threadIdx.x;

    if (bid == 0)
        initA_body(sm, red, init_deter, w_po, g_po, bb_po, w_ps, b_ps);
    grid_sync();

    // init xcat for t=0 (1 row/CTA)
    {
        float* x36 = sm + 1408;
        const int b = bid;
        const int f = is_first[(size_t)b * Tv];
        if (tid < 32) x36[tid] = g_init[DETERv + tid];
        else if (tid < 36) x36[tid] = (f > 0) ? 0.f : action[(size_t)b * Tv * ACTv + (tid - 32)];
        __syncthreads();
        prior_in_body(x36, red, b, w_pi, g_pi, bb_pi);
        float* xc = g_xcat + (size_t)b * 1024;
#pragma unroll
        for (int i = 0; i < 2; i++) {
            int j = tid + 256 * i;
            xc[512 + j] = g_init[j];
        }
        __syncthreads();
    }
    grid_sync();

    for (int t = 0; t < Tv; t++) {
        gates_body(sm, bid, w_gru);
        grid_sync();

        gru_row_body(sm, red, bid, g_g, bb_g, out, t);
        grid_sync();

        mm_body(sm, bid, w_po, w_post, obs, t);
        grid_sync();

        tail_row_body(sm, red, bid,
                      g_po, bb_po, g_pq, bb_pq,
                      w_ps, b_ps, w_qs, b_qs,
                      w_pi, g_pi, bb_pi,
                      action, is_first, out, t);
        grid_sync();
    }
}

extern "C" void kernel_launch(void* const* d_in, const int* in_sizes, int n_in,
                              void* d_out, int out_size)
{
    const float* obs        = (const float*)d_in[0];
    const float* action     = (const float*)d_in[1];
    const int*   is_first   = (const int*)d_in[2];
    const float* w_prior_in = (const float*)d_in[3];
    const float* g_prior_in = (const float*)d_in[4];
    const float* bb_prior_in= (const float*)d_in[5];
    const float* w_gru      = (const float*)d_in[6];
    const float* g_gru_p    = (const float*)d_in[7];
    const float* bb_gru_p   = (const float*)d_in[8];
    const float* w_prior_out= (const float*)d_in[9];
    const float* g_prior_out= (const float*)d_in[10];
    const float* bb_prior_out=(const float*)d_in[11];
    const float* w_prior_st = (const float*)d_in[12];
    const float* b_prior_st = (const float*)d_in[13];
    const float* w_post     = (const float*)d_in[14];
    const float* g_post     = (const float*)d_in[15];
    const float* bb_post    = (const float*)d_in[16];
    const float* w_post_st  = (const float*)d_in[17];
    const float* b_post_st  = (const float*)d_in[18];
    const float* init_deter = (const float*)d_in[19];
    float* out = (float*)d_out;

    k_rssm<<<NB, 256>>>(obs, action, is_first,
                        w_prior_in, g_prior_in, bb_prior_in,
                        w_gru, g_gru_p, bb_gru_p,
                        w_prior_out, g_prior_out, bb_prior_out,
                        w_prior_st, b_prior_st,
                        w_post, g_post, bb_post,
                        w_post_st, b_post_st,
                        init_deter, out);
}

// round 12
// speedup vs baseline: 1.7173x; 1.1717x over previous
#include <cuda_runtime.h>
#include <math.h>

#define Bv 256
#define Tv 256
#define STOCHv 32
#define DETERv 512
#define HIDv 512
#define OBSv 18
#define ACTv 4
#define GATESv 1536
#define OUTCv 1216
#define NB 256

__device__ float g_xcat[Bv * 1024];        // [b][0:512]=h(t), [512:1024]=deter_in(t)
__device__ float g_gates[8][Bv * GATESv];  // gates split-K partials
__device__ float g_mm[2][8][Bv * HIDv];    // mm split-K partials
__device__ float g_h23[2][Bv * HIDv];      // post-LN h2/h3
__device__ float g_deter[Bv * DETERv];
__device__ float g_init[DETERv + STOCHv];  // deter0, init_mean
__device__ unsigned g_bar_count;
__device__ unsigned g_bar_gen;

typedef unsigned long long u64;

static __device__ __forceinline__ u64 ffma2(u64 a, u64 b, u64 c) {
    u64 d; asm("fma.rn.f32x2 %0, %1, %2, %3;" : "=l"(d) : "l"(a), "l"(b), "l"(c));
    return d;
}
static __device__ __forceinline__ u64 dup2(float x) {
    u64 r; asm("mov.b64 %0, {%1, %1};" : "=l"(r) : "f"(x)); return r;
}
static __device__ __forceinline__ u64 f2u(float x, float y) {
    u64 v; asm("mov.b64 %0, {%1, %2};" : "=l"(v) : "f"(x), "f"(y)); return v;
}
static __device__ __forceinline__ float2 u2f(u64 v) {
    float2 f; asm("mov.b64 {%0, %1}, %2;" : "=f"(f.x), "=f"(f.y) : "l"(v)); return f;
}
static __device__ __forceinline__ float sigm(float x)  { return 1.f / (1.f + expf(-x)); }
static __device__ __forceinline__ float siluf(float x) { return x / (1.f + expf(-x)); }
static __device__ __forceinline__ float softp(float x) { return (x > 20.f) ? x : log1pf(expf(x)); }

static __device__ __forceinline__ void grid_sync() {
    __syncthreads();
    if (threadIdx.x == 0) {
        unsigned gen = *((volatile unsigned*)&g_bar_gen);
        __threadfence();
        if (atomicAdd(&g_bar_count, 1u) == NB - 1) {
            *((volatile unsigned*)&g_bar_count) = 0;
            __threadfence();
            atomicExch(&g_bar_gen, gen + 1);
        } else {
            while (*((volatile unsigned*)&g_bar_gen) == gen) { }
        }
        __threadfence();
    }
    __syncthreads();
}

static __device__ __forceinline__ float block_sum_256(float v, float* red) {
    int lane = threadIdx.x & 31, wid = threadIdx.x >> 5;
#pragma unroll
    for (int o = 16; o; o >>= 1) v += __shfl_xor_sync(0xffffffffu, v, o);
    __syncthreads();
    if (lane == 0) red[wid] = v;
    __syncthreads();
    float s = ((red[0] + red[1]) + (red[2] + red[3]))
            + ((red[4] + red[5]) + (red[6] + red[7]));
    return s;
}

// ---------------- init A (CTA 0) ----------------
static __device__ void initA_body(
    float* sm, float* red,
    const float* __restrict__ initial_deter,
    const float* __restrict__ w_po, const float* __restrict__ g_po, const float* __restrict__ bb_po,
    const float* __restrict__ w_ps, const float* __restrict__ b_ps)
{
    const int tid = threadIdx.x;
    float* d0s = sm;
    float* h0s = sm + 512;
#pragma unroll
    for (int i = 0; i < 2; i++) {
        int j = tid + 256 * i;
        float v = tanhf(initial_deter[j]);
        d0s[j] = v; g_init[j] = v;
    }
    __syncthreads();
    float p[2] = {0.f, 0.f};
    for (int k = 0; k < 512; k++) {
        float dv = d0s[k];
#pragma unroll
        for (int i = 0; i < 2; i++) p[i] += dv * w_po[(size_t)k * 512 + tid + 256 * i];
    }
    float mean = block_sum_256(p[0] + p[1], red) * (1.f / 512.f);
    float e[2], vs = 0.f;
#pragma unroll
    for (int i = 0; i < 2; i++) { e[i] = p[i] - mean; vs += e[i] * e[i]; }
    float var = block_sum_256(vs, red) * (1.f / 512.f);
    float rstd = rsqrtf(var + 1e-3f);
#pragma unroll
    for (int i = 0; i < 2; i++) {
        int j = tid + 256 * i;
        h0s[j] = siluf(e[i] * rstd * g_po[j] + bb_po[j]);
    }
    __syncthreads();
    if (tid < STOCHv) {
        float s0 = 0.f, s1 = 0.f, s2 = 0.f, s3 = 0.f;
        for (int k = 0; k < 512; k += 4) {
            s0 += h0s[k]     * w_ps[(size_t)k * 64 + tid];
            s1 += h0s[k + 1] * w_ps[(size_t)(k + 1) * 64 + tid];
            s2 += h0s[k + 2] * w_ps[(size_t)(k + 2) * 64 + tid];
            s3 += h0s[k + 3] * w_ps[(size_t)(k + 3) * 64 + tid];
        }
        g_init[DETERv + tid] = b_ps[tid] + ((s0 + s1) + (s2 + s3));
    }
    __syncthreads();
}

// prior_in for one row (init only), x36 in smem
static __device__ void prior_in_body(
    float* x36, float* red, int b,
    const float* __restrict__ w_pi, const float* __restrict__ g_pi, const float* __restrict__ bb_pi)
{
    const int tid = threadIdx.x;
    float p[2] = {0.f, 0.f};
#pragma unroll
    for (int k = 0; k < 36; k++) {
        float xv = x36[k];
#pragma unroll
        for (int i = 0; i < 2; i++) p[i] += xv * w_pi[(size_t)k * HIDv + tid + 256 * i];
    }
    float mean = block_sum_256(p[0] + p[1], red) * (1.f / 512.f);
    float e[2], vs = 0.f;
#pragma unroll
    for (int i = 0; i < 2; i++) { e[i] = p[i] - mean; vs += e[i] * e[i]; }
    float var = block_sum_256(vs, red) * (1.f / 512.f);
    float rstd = rsqrtf(var + 1e-3f);
    float* xc = g_xcat + (size_t)b * 1024;
#pragma unroll
    for (int i = 0; i < 2; i++) {
        int j = tid + 256 * i;
        xc[j] = siluf(e[i] * rstd * g_pi[j] + bb_pi[j]);
    }
}

// ---- gates GEMM [256,1024]@[1024,1536]: 2M(128) x 16N(96) x ksplit8(K=128) ----
// M-packed f32x2: acc[p][c] = rows (2p,2p+1) of col c. TMp=4, TN=6.
// AS_S MUST be a multiple of 4 so float4 A-frag loads stay 16B-aligned for all k.
#define AS_S 132
#define BS_SG 100
static __device__ void gates_body(float* sm, int bid, const float* __restrict__ w_gru)
{
    float* As = sm;           // [16][132]
    float* Bs = sm + 2112;    // [16][100]
    const int tid = threadIdx.x;
    const int row0 = (bid & 1) * 128;
    const int col0 = ((bid >> 1) & 15) * 96;
    const int kz   = bid >> 5;
    const int K0   = kz * 128;
    const int tx = tid & 15, ty = tid >> 4;

    u64 acc[4][6];
#pragma unroll
    for (int p = 0; p < 4; p++)
#pragma unroll
        for (int c = 0; c < 6; c++) acc[p][c] = 0ull;

    const int ar = tid >> 1, akg = (tid & 1) * 8;
    const float* Ap = g_xcat + (size_t)(row0 + ar) * 1024 + K0 + akg;
    // B: 384 float4; slot tid + (tid<128 ? tid+256)
    const int bk0 = tid / 24,         bn0 = (tid % 24) * 4;
    const bool hasB1 = (tid < 128);
    const int bk1 = (tid + 256) / 24, bn1 = ((tid + 256) % 24) * 4;
    const float* Bp0 = w_gru + (size_t)(K0 + bk0) * GATESv + col0 + bn0;
    const float* Bp1 = w_gru + (size_t)(K0 + bk1) * GATESv + col0 + bn1;

    float4 a0 = *(const float4*)Ap;
    float4 a1 = *(const float4*)(Ap + 4);
    float4 b0 = *(const float4*)Bp0;
    float4 b1 = hasB1 ? *(const float4*)Bp1 : make_float4(0.f, 0.f, 0.f, 0.f);

    for (int kt = 0; kt < 8; kt++) {
        {
            float v[8] = {a0.x, a0.y, a0.z, a0.w, a1.x, a1.y, a1.z, a1.w};
#pragma unroll
            for (int j = 0; j < 8; j++) As[(akg + j) * AS_S + ar] = v[j];
        }
        *(float4*)&Bs[bk0 * BS_SG + bn0] = b0;
        if (hasB1) *(float4*)&Bs[bk1 * BS_SG + bn1] = b1;
        __syncthreads();
        if (kt + 1 < 8) {
            a0 = *(const float4*)(Ap + (size_t)(kt + 1) * 16);
            a1 = *(const float4*)(Ap + (size_t)(kt + 1) * 16 + 4);
            b0 = *(const float4*)(Bp0 + (size_t)(kt + 1) * 16 * GATESv);
            if (hasB1) b1 = *(const float4*)(Bp1 + (size_t)(kt + 1) * 16 * GATESv);
        }
#pragma unroll 4
        for (int k = 0; k < 16; k++) {
            const float4* apf = (const float4*)(As + k * AS_S + ty * 8);
            float4 A0 = apf[0], A1 = apf[1];
            u64 ap[4] = {f2u(A0.x, A0.y), f2u(A0.z, A0.w),
                         f2u(A1.x, A1.y), f2u(A1.z, A1.w)};
#pragma unroll
            for (int q = 0; q < 3; q++) {
                float2 bq = *(const float2*)(Bs + k * BS_SG + 2 * tx + 32 * q);
                u64 d0 = dup2(bq.x), d1 = dup2(bq.y);
#pragma unroll
                for (int p = 0; p < 4; p++) {
                    acc[p][2 * q]     = ffma2(ap[p], d0, acc[p][2 * q]);
                    acc[p][2 * q + 1] = ffma2(ap[p], d1, acc[p][2 * q + 1]);
                }
            }
        }
        __syncthreads();
    }
    // store: rows ty*8+2p+(0/1); cols col0 + 2tx + 32q + (0/1)
    float* G = g_gates[kz];
#pragma unroll
    for (int p = 0; p < 4; p++) {
        float2 c0v = u2f(acc[p][0]), c1v = u2f(acc[p][1]);
        float2 c2v = u2f(acc[p][2]), c3v = u2f(acc[p][3]);
        float2 c4v = u2f(acc[p][4]), c5v = u2f(acc[p][5]);
        size_t rA = (size_t)(row0 + ty * 8 + 2 * p) * GATESv + col0 + 2 * tx;
        size_t rB = rA + GATESv;
        *(float2*)&G[rA]      = make_float2(c0v.x, c1v.x);
        *(float2*)&G[rA + 32] = make_float2(c2v.x, c3v.x);
        *(float2*)&G[rA + 64] = make_float2(c4v.x, c5v.x);
        *(float2*)&G[rB]      = make_float2(c0v.y, c1v.y);
        *(float2*)&G[rB + 32] = make_float2(c2v.y, c3v.y);
        *(float2*)&G[rB + 64] = make_float2(c4v.y, c5v.y);
    }
}

// ---- GRU for row b (1 row/CTA) ----
static __device__ void gru_row_body(
    float* gs, float* red, int b,
    const float* __restrict__ g_g, const float* __restrict__ bb_g,
    float* __restrict__ out, int t)
{
    const int tid = threadIdx.x;
    float s = 0.f;
#pragma unroll
    for (int i = 0; i < 6; i++) {
        int c = tid + 256 * i;
        float v = 0.f;
#pragma unroll
        for (int kz = 0; kz < 8; kz++) v += g_gates[kz][(size_t)b * GATESv + c];
        gs[c] = v; s += v;
    }
    float mean = block_sum_256(s, red) * (1.f / 1536.f);
    float vs = 0.f;
#pragma unroll
    for (int i = 0; i < 6; i++) {
        float e = gs[tid + 256 * i] - mean; vs += e * e;
    }
    float var = block_sum_256(vs, red) * (1.f / 1536.f);
    float rstd = rsqrtf(var + 1e-3f);

    float* ob = out + ((size_t)b * Tv + t) * OUTCv;
    const float* xc = g_xcat + (size_t)b * 1024 + 512;
#pragma unroll
    for (int i = 0; i < 2; i++) {
        int j = tid + 256 * i;
        float gr = (gs[j] - mean) * rstd * g_g[j] + bb_g[j];
        float gc = (gs[j + 512] - mean) * rstd * g_g[j + 512] + bb_g[j + 512];
        float gu = (gs[j + 1024] - mean) * rstd * g_g[j + 1024] + bb_g[j + 1024];
        float r = sigm(gr);
        float u = sigm(gu - 1.0f);
        float cand = siluf(r * gc);
        float d = u * cand + (1.f - u) * xc[j];
        g_deter[(size_t)b * 512 + j] = d;
        ob[j] = d;
        ob[608 + j] = d;
    }
}

// ---- mm GEMMs: 2M(128) x 8N(64) x 2z x ksplit8(K=64); TMp=4, TN=4 ----
#define BS_SM 68
static __device__ void mm_body(
    float* sm, int bid,
    const float* __restrict__ w_po, const float* __restrict__ w_post,
    const float* __restrict__ obs, int t)
{
    float* As = sm;           // [16][132]
    float* Bs = sm + 2112;    // [16][68]
    const int tid = threadIdx.x;
    const int m2 = bid & 1;
    const int c0 = ((bid >> 1) & 7) * 64;
    const int z  = (bid >> 4) & 1;
    const int kz = bid >> 5;
    const int K0 = kz * 64;
    const int tx = tid & 15, ty = tid >> 4;
    const float* W = z ? w_post : w_po;

    u64 acc[4][4];
#pragma unroll
    for (int p = 0; p < 4; p++)
#pragma unroll
        for (int c = 0; c < 4; c++) acc[p][c] = 0ull;

    const int ar = tid >> 1, akg = (tid & 1) * 8;
    const float* Ap = g_deter + (size_t)(m2 * 128 + ar) * 512 + K0 + akg;
    const int bk = tid >> 4, bn = (tid & 15) * 4;   // 256 f4, 1/thread
    const float* Bp = W + (size_t)(K0 + bk) * 512 + c0 + bn;

    float4 a0 = *(const float4*)Ap;
    float4 a1 = *(const float4*)(Ap + 4);
    float4 b0 = *(const float4*)Bp;

    for (int kt = 0; kt < 4; kt++) {
        {
            float v[8] = {a0.x, a0.y, a0.z, a0.w, a1.x, a1.y, a1.z, a1.w};
#pragma unroll
            for (int j = 0; j < 8; j++) As[(akg + j) * AS_S + ar] = v[j];
        }
        *(float4*)&Bs[bk * BS_SM + bn] = b0;
        __syncthreads();
        if (kt + 1 < 4) {
            a0 = *(const float4*)(Ap + (size_t)(kt + 1) * 16);
            a1 = *(const float4*)(Ap + (size_t)(kt + 1) * 16 + 4);
            b0 = *(const float4*)(Bp + (size_t)(kt + 1) * 16 * 512);
        }
#pragma unroll 4
        for (int k = 0; k < 16; k++) {
            const float4* apf = (const float4*)(As + k * AS_S + ty * 8);
            float4 A0 = apf[0], A1 = apf[1];
            u64 ap[4] = {f2u(A0.x, A0.y), f2u(A0.z, A0.w),
                         f2u(A1.x, A1.y), f2u(A1.z, A1.w)};
#pragma unroll
            for (int q = 0; q < 2; q++) {
                float2 bq = *(const float2*)(Bs + k * BS_SM + 2 * tx + 32 * q);
                u64 d0 = dup2(bq.x), d1 = dup2(bq.y);
#pragma unroll
                for (int p = 0; p < 4; p++) {
                    acc[p][2 * q]     = ffma2(ap[p], d0, acc[p][2 * q]);
                    acc[p][2 * q + 1] = ffma2(ap[p], d1, acc[p][2 * q + 1]);
                }
            }
        }
        __syncthreads();
    }

    if (z == 1 && kz == 7) {   // obs tail: K rows 512..529 of w_post
        float* obs_s = sm;          // [18][132] = 2376
        float* wb_s  = sm + 2400;   // [18][68]
#pragma unroll
        for (int q = 0; q < 9; q++) {
            int e = q * 256 + tid;          // 2304 = 128*18
            int row = e / 18, k = e % 18;
            obs_s[k * AS_S + row] = obs[((size_t)(m2 * 128 + row) * Tv + t) * OBSv + k];
        }
#pragma unroll
        for (int q = 0; q < 5; q++) {
            int e = q * 256 + tid;          // 1152 = 18*64
            if (e < 1152) {
                int k = e / 64, n = e % 64;
                wb_s[k * BS_SM + n] = w_post[(size_t)(512 + k) * 512 + c0 + n];
            }
        }
        __syncthreads();
#pragma unroll 2
        for (int k = 0; k < OBSv; k++) {
            u64 ap[4];
#pragma unroll
            for (int p = 0; p < 4; p++) {
                float2 av = *(const float2*)(obs_s + k * AS_S + ty * 8 + 2 * p);
                ap[p] = f2u(av.x, av.y);
            }
#pragma unroll
            for (int q = 0; q < 2; q++) {
                float2 bq = *(const float2*)(wb_s + k * BS_SM + 2 * tx + 32 * q);
                u64 d0 = dup2(bq.x), d1 = dup2(bq.y);
#pragma unroll
                for (int p = 0; p < 4; p++) {
                    acc[p][2 * q]     = ffma2(ap[p], d0, acc[p][2 * q]);
                    acc[p][2 * q + 1] = ffma2(ap[p], d1, acc[p][2 * q + 1]);
                }
            }
        }
        __syncthreads();
    }

    float* Gm = g_mm[z][kz];
#pragma unroll
    for (int p = 0; p < 4; p++) {
        float2 c0v = u2f(acc[p][0]), c1v = u2f(acc[p][1]);
        float2 c2v = u2f(acc[p][2]), c3v = u2f(acc[p][3]);
        size_t rA = (size_t)(m2 * 128 + ty * 8 + 2 * p) * 512 + c0 + 2 * tx;
        size_t rB = rA + 512;
        *(float2*)&Gm[rA]      = make_float2(c0v.x, c1v.x);
        *(float2*)&Gm[rA + 32] = make_float2(c2v.x, c3v.x);
        *(float2*)&Gm[rB]      = make_float2(c0v.y, c1v.y);
        *(float2*)&Gm[rB + 32] = make_float2(c2v.y, c3v.y);
    }
}

// ---- T1: reduce mm splits + LN + silu -> g_h23 (1 row/CTA) ----
static __device__ void t1_body(
    float* red, int b,
    const float* __restrict__ g_po, const float* __restrict__ bb_po,
    const float* __restrict__ g_pq, const float* __restrict__ bb_pq)
{
    const int tid = threadIdx.x;
#pragma unroll
    for (int z = 0; z < 2; z++) {
        float a[2] = {0.f, 0.f};
#pragma unroll
        for (int kz = 0; kz < 8; kz++) {
            const float* src = g_mm[z][kz] + (size_t)b * 512;
            a[0] += src[tid]; a[1] += src[tid + 256];
        }
        float mean = block_sum_256(a[0] + a[1], red) * (1.f / 512.f);
        float e[2], vs = 0.f;
#pragma unroll
        for (int i = 0; i < 2; i++) { e[i] = a[i] - mean; vs += e[i] * e[i]; }
        float var = block_sum_256(vs, red) * (1.f / 512.f);
        float rstd = rsqrtf(var + 1e-3f);
        const float* gg = z ? g_pq : g_po;
        const float* gb = z ? bb_pq : bb_po;
        float* hv = g_h23[z] + (size_t)b * 512;
        hv[tid]       = siluf(e[0] * rstd * gg[tid] + gb[tid]);
        hv[tid + 256] = siluf(e[1] * rstd * gg[tid + 256] + gb[tid + 256]);
        __syncthreads();
    }
}

// ---- T2: stats + outputs + prior_in + xcat for 4 rows (64 CTAs) ----
static __device__ void t2_body(
    float* sm, float* red, int bid,
    const float* __restrict__ w_ps, const float* __restrict__ b_ps,
    const float* __restrict__ w_qs, const float* __restrict__ b_qs,
    const float* __restrict__ w_pi, const float* __restrict__ g_pi, const float* __restrict__ bb_pi,
    const float* __restrict__ action, const int* __restrict__ is_first,
    float* __restrict__ out, int t)
{
    const int tid = threadIdx.x;
    float* hs    = sm;          // [2][512][4]  (z*2048 + k*4 + r)
    float* ppart = sm + 4096;   // [2][128][4]
    float* st    = sm + 5120;   // [128][4]
    float* x36s  = sm + 5632;   // [36][4]
    float* fs    = sm + 5780;   // [4]
    const int r0 = bid * 4;

    // stage h2/h3 for 4 rows
#pragma unroll
    for (int q = 0; q < 16; q++) {
        int e = q * 256 + tid;              // 4096
        int z = e >> 11, rem = e & 2047;
        int r = rem >> 9, k = rem & 511;
        hs[z * 2048 + k * 4 + r] = g_h23[z][(size_t)(r0 + r) * 512 + k];
    }
    if (tid < 4 && t + 1 < Tv) fs[tid] = (float)is_first[(size_t)(r0 + tid) * Tv + t + 1];
    __syncthreads();

    // stats: 128 outs x 2 k-halves
    {
        const int khalf = tid >> 7;
        const int j = tid & 127;
        const int zsel = j >> 6;
        const int jj = j & 63;
        const float* W = zsel ? w_qs : w_ps;
        const float* hb = hs + zsel * 2048;
        float a0 = 0.f, a1 = 0.f, a2 = 0.f, a3 = 0.f;
        const int kb = khalf * 256;
        for (int k = 0; k < 256; k++) {
            float w = W[(size_t)(kb + k) * 64 + jj];
            float4 h4 = *(const float4*)(hb + (kb + k) * 4);
            a0 += h4.x * w; a1 += h4.y * w; a2 += h4.z * w; a3 += h4.w * w;
        }
        float* pp = ppart + khalf * 512 + j * 4;
        pp[0] = a0; pp[1] = a1; pp[2] = a2; pp[3] = a3;
    }
    __syncthreads();
    if (tid < 128) {
        const int j = tid;
        const int zsel = j >> 6, jj = j & 63;
        float bias = zsel ? b_qs[jj] : b_ps[jj];
#pragma unroll
        for (int r = 0; r < 4; r++) {
            float s = ppart[j * 4 + r] + ppart[512 + j * 4 + r] + bias;
            st[j * 4 + r] = s;
            float* ob = out + ((size_t)(r0 + r) * Tv + t) * OUTCv;
            if (zsel == 0) {      // prior stats
                if (jj < 32) { ob[1120 + jj] = s; ob[1152 + jj] = s; }
                else          ob[1184 + jj - 32] = softp(s) + 0.1f;
            } else {              // post stats
                if (jj < 32) { ob[512 + jj] = s; ob[544 + jj] = s; }
                else          ob[576 + jj - 32] = softp(s) + 0.1f;
            }
        }
    }
    __syncthreads();

    if (t + 1 >= Tv) return;

    // build x36 for 4 rows
    if (tid < 144) {
        int k = tid >> 2, r = tid & 3;
        bool f = fs[r] > 0.f;
        float v;
        if (k < 32) v = f ? g_init[DETERv + k] : st[(64 + k) * 4 + r];
        else        v = f ? 0.f : action[((size_t)(r0 + r) * Tv + t + 1) * ACTv + (k - 32)];
        x36s[k * 4 + r] = v;
    }
    __syncthreads();

    // prior_in GEMV: 512 outs, 2 per thread, 4 rows
    float acc[4][2];
#pragma unroll
    for (int r = 0; r < 4; r++) { acc[r][0] = 0.f; acc[r][1] = 0.f; }
#pragma unroll 4
    for (int k = 0; k < 36; k++) {
        float4 x4 = *(const float4*)(x36s + k * 4);
        float w0 = w_pi[(size_t)k * HIDv + tid];
        float w1 = w_pi[(size_t)k * HIDv + tid + 256];
        acc[0][0] += x4.x * w0; acc[0][1] += x4.x * w1;
        acc[1][0] += x4.y * w0; acc[1][1] += x4.y * w1;
        acc[2][0] += x4.z * w0; acc[2][1] += x4.z * w1;
        acc[3][0] += x4.w * w0; acc[3][1] += x4.w * w1;
    }
#pragma unroll
    for (int r = 0; r < 4; r++) {
        float mean = block_sum_256(acc[r][0] + acc[r][1], red) * (1.f / 512.f);
        float e0 = acc[r][0] - mean, e1 = acc[r][1] - mean;
        float var = block_sum_256(e0 * e0 + e1 * e1, red) * (1.f / 512.f);
        float rstd = rsqrtf(var + 1e-3f);
        float* xc = g_xcat + (size_t)(r0 + r) * 1024;
        xc[tid]       = siluf(e0 * rstd * g_pi[tid] + bb_pi[tid]);
        xc[tid + 256] = siluf(e1 * rstd * g_pi[tid + 256] + bb_pi[tid + 256]);
        bool f = fs[r] > 0.f;
        const float* dsrc = g_deter + (size_t)(r0 + r) * 512;
#pragma unroll
        for (int i = 0; i < 2; i++) {
            int j = tid + 256 * i;
            xc[512 + j] = f ? g_init[j] : dsrc[j];
        }
    }
}

// ---------------- persistent kernel ----------------
__global__ __launch_bounds__(256, 2) void k_rssm(
    const float* __restrict__ obs, const float* __restrict__ action,
    const int* __restrict__ is_first,
    const float* __restrict__ w_pi, const float* __restrict__ g_pi, const float* __restrict__ bb_pi,
    const float* __restrict__ w_gru, const float* __restrict__ g_g, const float* __restrict__ bb_g,
    const float* __restrict__ w_po, const float* __restrict__ g_po, const float* __restrict__ bb_po,
    const float* __restrict__ w_ps, const float* __restrict__ b_ps,
    const float* __restrict__ w_post, const float* __restrict__ g_pq, const float* __restrict__ bb_pq,
    const float* __restrict__ w_qs, const float* __restrict__ b_qs,
    const float* __restrict__ init_deter,
    float* __restrict__ out)
{
    __shared__ float sm[6008];
    float* red = sm + 6000;
    const int bid = blockIdx.x;
    const int tid = threadIdx.x;

    if (bid == 0)
        initA_body(sm, red, init_deter, w_po, g_po, bb_po, w_ps, b_ps);
    grid_sync();

    {   // init xcat for t=0 (1 row/CTA)
        float* x36 = sm + 5632;
        const int b = bid;
        const int f = is_first[(size_t)b * Tv];
        if (tid < 32) x36[tid] = g_init[DETERv + tid];
        else if (tid < 36) x36[tid] = (f > 0) ? 0.f : action[(size_t)b * Tv * ACTv + (tid - 32)];
        __syncthreads();
        prior_in_body(x36, red, b, w_pi, g_pi, bb_pi);
        float* xc = g_xcat + (size_t)b * 1024;
#pragma unroll
        for (int i = 0; i < 2; i++) {
            int j = tid + 256 * i;
            xc[512 + j] = g_init[j];
        }
        __syncthreads();
    }
    grid_sync();

    for (int t = 0; t < Tv; t++) {
        gates_body(sm, bid, w_gru);
        grid_sync();

        gru_row_body(sm, red, bid, g_g, bb_g, out, t);
        grid_sync();

        mm_body(sm, bid, w_po, w_post, obs, t);
        grid_sync();

        t1_body(red, bid, g_po, bb_po, g_pq, bb_pq);
        grid_sync();

        if (bid < 64)
            t2_body(sm, red, bid, w_ps, b_ps, w_qs, b_qs,
                    w_pi, g_pi, bb_pi, action, is_first, out, t);
        grid_sync();
    }
}

extern "C" void kernel_launch(void* const* d_in, const int* in_sizes, int n_in,
                              void* d_out, int out_size)
{
    const float* obs        = (const float*)d_in[0];
    const float* action     = (const float*)d_in[1];
    const int*   is_first   = (const int*)d_in[2];
    const float* w_prior_in = (const float*)d_in[3];
    const float* g_prior_in = (const float*)d_in[4];
    const float* bb_prior_in= (const float*)d_in[5];
    const float* w_gru      = (const float*)d_in[6];
    const float* g_gru_p    = (const float*)d_in[7];
    const float* bb_gru_p   = (const float*)d_in[8];
    const float* w_prior_out= (const float*)d_in[9];
    const float* g_prior_out= (const float*)d_in[10];
    const float* bb_prior_out=(const float*)d_in[11];
    const float* w_prior_st = (const float*)d_in[12];
    const float* b_prior_st = (const float*)d_in[13];
    const float* w_post     = (const float*)d_in[14];
    const float* g_post     = (const float*)d_in[15];
    const float* bb_post    = (const float*)d_in[16];
    const float* w_post_st  = (const float*)d_in[17];
    const float* b_post_st  = (const float*)d_in[18];
    const float* init_deter = (const float*)d_in[19];
    float* out = (float*)d_out;

    k_rssm<<<NB, 256>>>(obs, action, is_first,
                        w_prior_in, g_prior_in, bb_prior_in,
                        w_gru, g_gru_p, bb_gru_p,
                        w_prior_out, g_prior_out, bb_prior_out,
                        w_prior_st, b_prior_st,
                        w_post, g_post, bb_post,
                        w_post_st, b_post_st,
                        init_deter, out);
}